// round 4
// baseline (speedup 1.0000x reference)
#include <cuda_runtime.h>

// ---------------------------------------------------------------------------
// Problem constants
// ---------------------------------------------------------------------------
#define EDIM   1024
#define NAQ    128
#define BSZ    256
#define NROWS  (BSZ * NAQ)          // 32768
#define QKVDIM 3072
#define HEADS  16
#define HDIM   64
#define NBH    (BSZ * HEADS)        // 4096 attention batches
#define OUT_ELEMS (NROWS * EDIM)    // 33554432 floats of `out`, then avg_w

// ---------------------------------------------------------------------------
// Scratch (device globals: allocation-free)
// ---------------------------------------------------------------------------
__device__ float g_xn  [(size_t)NROWS * EDIM];     // 128 MB: ln1(x)
__device__ float g_qkv [(size_t)NROWS * QKVDIM];   // 384 MB: qkv (q scaled)
__device__ float g_attn[(size_t)NROWS * EDIM];     // 128 MB: attention output

// ---------------------------------------------------------------------------
// Packed f32x2 helpers (Blackwell sm_103a)
// ---------------------------------------------------------------------------
__device__ __forceinline__ unsigned long long pack2(float lo, float hi) {
    unsigned long long r;
    asm("mov.b64 %0, {%1, %2};"
        : "=l"(r) : "r"(__float_as_uint(lo)), "r"(__float_as_uint(hi)));
    return r;
}
__device__ __forceinline__ float2 unpack2(unsigned long long v) {
    unsigned int lo, hi;
    asm("mov.b64 {%0, %1}, %2;" : "=r"(lo), "=r"(hi) : "l"(v));
    return make_float2(__uint_as_float(lo), __uint_as_float(hi));
}
__device__ __forceinline__ unsigned long long ffma2(
    unsigned long long a, unsigned long long b, unsigned long long c) {
    unsigned long long d;
    asm("fma.rn.f32x2 %0, %1, %2, %3;" : "=l"(d) : "l"(a), "l"(b), "l"(c));
    return d;
}

// ---------------------------------------------------------------------------
// LayerNorm kernel: out = LN(in [+ res]) * w + b.  One block per 1024-row.
// ---------------------------------------------------------------------------
__global__ __launch_bounds__(256) void ln_kernel(
    const float* __restrict__ in, const float* __restrict__ res,
    const float* __restrict__ w, const float* __restrict__ b,
    float* __restrict__ out)
{
    __shared__ float red_s[8];
    __shared__ float red_q[8];
    size_t row = blockIdx.x;
    int t = threadIdx.x;

    const float4* px = (const float4*)(in + row * EDIM);
    float4 v = px[t];
    if (res != nullptr) {
        const float4* pr = (const float4*)(res + row * EDIM);
        float4 rv = pr[t];
        v.x += rv.x; v.y += rv.y; v.z += rv.z; v.w += rv.w;
    }
    float s = v.x + v.y + v.z + v.w;
    float q = v.x * v.x + v.y * v.y + v.z * v.z + v.w * v.w;
#pragma unroll
    for (int o = 16; o > 0; o >>= 1) {
        s += __shfl_xor_sync(0xffffffffu, s, o);
        q += __shfl_xor_sync(0xffffffffu, q, o);
    }
    if ((t & 31) == 0) { red_s[t >> 5] = s; red_q[t >> 5] = q; }
    __syncthreads();
    float tot = 0.f, totq = 0.f;
#pragma unroll
    for (int k = 0; k < 8; ++k) { tot += red_s[k]; totq += red_q[k]; }

    float mean = tot * (1.0f / EDIM);
    float var  = totq * (1.0f / EDIM) - mean * mean;
    float rstd = rsqrtf(var + 1e-5f);

    int c0 = t * 4;
    float4 wv = *(const float4*)(w + c0);
    float4 bv = *(const float4*)(b + c0);
    float4 o4;
    o4.x = (v.x - mean) * rstd * wv.x + bv.x;
    o4.y = (v.y - mean) * rstd * wv.y + bv.y;
    o4.z = (v.z - mean) * rstd * wv.z + bv.z;
    o4.w = (v.w - mean) * rstd * wv.w + bv.w;
    ((float4*)(out + row * EDIM))[t] = o4;
}

// ---------------------------------------------------------------------------
// QKV GEMM: C[m,n] = (sum_k A[m,k] * W[n,k] + bias[n]) * (n<1024 ? 0.125 : 1)
// A = g_xn (32768 x 1024), W = in_w (3072 x 1024), C = g_qkv (32768 x 3072).
// 128x128 block tile, BK=16, 256 threads, 8x8 per thread via packed f32x2.
// ---------------------------------------------------------------------------
__global__ __launch_bounds__(256) void qkv_gemm_kernel(
    const float* __restrict__ A, const float* __restrict__ W,
    const float* __restrict__ bias, float* __restrict__ C)
{
    __shared__ float As[2][16][132];
    __shared__ float Bs[2][16][132];

    int t  = threadIdx.x;
    int bn = blockIdx.x;   // 0..23  (N blocks)
    int bm = blockIdx.y;   // 0..255 (M blocks)

    const float* Ab = A + (size_t)bm * 128 * 1024;
    const float* Wb = W + (size_t)bn * 128 * 1024;

    int lrow = t >> 2;          // 0..63
    int lk   = (t & 3) << 2;    // 0,4,8,12
    int tm   = t >> 4;          // 0..15
    int tn   = t & 15;          // 0..15

    unsigned long long acc[8][4];
#pragma unroll
    for (int i = 0; i < 8; ++i)
#pragma unroll
        for (int j = 0; j < 4; ++j) acc[i][j] = 0ull;

    // preload tile 0
    float4 a0 = *(const float4*)&Ab[lrow * 1024 + lk];
    float4 a1 = *(const float4*)&Ab[(lrow + 64) * 1024 + lk];
    float4 b0 = *(const float4*)&Wb[lrow * 1024 + lk];
    float4 b1 = *(const float4*)&Wb[(lrow + 64) * 1024 + lk];
    As[0][lk + 0][lrow] = a0.x; As[0][lk + 1][lrow] = a0.y;
    As[0][lk + 2][lrow] = a0.z; As[0][lk + 3][lrow] = a0.w;
    As[0][lk + 0][lrow + 64] = a1.x; As[0][lk + 1][lrow + 64] = a1.y;
    As[0][lk + 2][lrow + 64] = a1.z; As[0][lk + 3][lrow + 64] = a1.w;
    Bs[0][lk + 0][lrow] = b0.x; Bs[0][lk + 1][lrow] = b0.y;
    Bs[0][lk + 2][lrow] = b0.z; Bs[0][lk + 3][lrow] = b0.w;
    Bs[0][lk + 0][lrow + 64] = b1.x; Bs[0][lk + 1][lrow + 64] = b1.y;
    Bs[0][lk + 2][lrow + 64] = b1.z; Bs[0][lk + 3][lrow + 64] = b1.w;
    __syncthreads();

    for (int kt = 0; kt < 64; ++kt) {
        int cur = kt & 1;
        if (kt + 1 < 64) {
            int k0 = (kt + 1) << 4;
            a0 = *(const float4*)&Ab[lrow * 1024 + k0 + lk];
            a1 = *(const float4*)&Ab[(lrow + 64) * 1024 + k0 + lk];
            b0 = *(const float4*)&Wb[lrow * 1024 + k0 + lk];
            b1 = *(const float4*)&Wb[(lrow + 64) * 1024 + k0 + lk];
        }
#pragma unroll
        for (int kk = 0; kk < 16; ++kk) {
            float4 fa0 = *(const float4*)&As[cur][kk][tm * 8];
            float4 fa1 = *(const float4*)&As[cur][kk][tm * 8 + 4];
            ulonglong2 fb0 = *(const ulonglong2*)&Bs[cur][kk][tn * 8];
            ulonglong2 fb1 = *(const ulonglong2*)&Bs[cur][kk][tn * 8 + 4];
            float av[8] = {fa0.x, fa0.y, fa0.z, fa0.w, fa1.x, fa1.y, fa1.z, fa1.w};
#pragma unroll
            for (int i = 0; i < 8; ++i) {
                unsigned long long ap = pack2(av[i], av[i]);
                acc[i][0] = ffma2(ap, fb0.x, acc[i][0]);
                acc[i][1] = ffma2(ap, fb0.y, acc[i][1]);
                acc[i][2] = ffma2(ap, fb1.x, acc[i][2]);
                acc[i][3] = ffma2(ap, fb1.y, acc[i][3]);
            }
        }
        if (kt + 1 < 64) {
            int nxt = cur ^ 1;
            As[nxt][lk + 0][lrow] = a0.x; As[nxt][lk + 1][lrow] = a0.y;
            As[nxt][lk + 2][lrow] = a0.z; As[nxt][lk + 3][lrow] = a0.w;
            As[nxt][lk + 0][lrow + 64] = a1.x; As[nxt][lk + 1][lrow + 64] = a1.y;
            As[nxt][lk + 2][lrow + 64] = a1.z; As[nxt][lk + 3][lrow + 64] = a1.w;
            Bs[nxt][lk + 0][lrow] = b0.x; Bs[nxt][lk + 1][lrow] = b0.y;
            Bs[nxt][lk + 2][lrow] = b0.z; Bs[nxt][lk + 3][lrow] = b0.w;
            Bs[nxt][lk + 0][lrow + 64] = b1.x; Bs[nxt][lk + 1][lrow + 64] = b1.y;
            Bs[nxt][lk + 2][lrow + 64] = b1.z; Bs[nxt][lk + 3][lrow + 64] = b1.w;
        }
        __syncthreads();
    }

    int m0 = bm * 128 + tm * 8;
    int n0 = bn * 128 + tn * 8;
    float4 bv0 = *(const float4*)&bias[n0];
    float4 bv1 = *(const float4*)&bias[n0 + 4];
    float scale = (n0 < 1024) ? 0.125f : 1.0f;   // q * HD^-0.5
#pragma unroll
    for (int i = 0; i < 8; ++i) {
        float2 c0 = unpack2(acc[i][0]);
        float2 c1 = unpack2(acc[i][1]);
        float2 c2 = unpack2(acc[i][2]);
        float2 c3 = unpack2(acc[i][3]);
        float4 o0 = make_float4((c0.x + bv0.x) * scale, (c0.y + bv0.y) * scale,
                                (c1.x + bv0.z) * scale, (c1.y + bv0.w) * scale);
        float4 o1 = make_float4((c2.x + bv1.x) * scale, (c2.y + bv1.y) * scale,
                                (c3.x + bv1.z) * scale, (c3.y + bv1.w) * scale);
        float* cp = C + (size_t)(m0 + i) * QKVDIM + n0;
        *(float4*)cp       = o0;
        *(float4*)(cp + 4) = o1;
    }
}

// ---------------------------------------------------------------------------
// Attention: one block per bh in [0,4096).
//   bh = (b%2)*2048 + n*16 + h ; sequence index i maps to original batch 2i+p.
//   q/k/v row for (bh, i): g_qkv[((2i+p)*128 + n)*3072 + {0,1024,2048} + h*64]
// SMEM: Qt[64][132] (d-major), Kt[64][132], Vs[128][68], S[128][132].
// ---------------------------------------------------------------------------
#define QT_OFF 0
#define KT_OFF (64 * 132)
#define V_OFF  (2 * 64 * 132)
#define S_OFF  (V_OFF + 128 * 68)
#define ATTN_SMEM_FLOATS (S_OFF + 128 * 132)
#define ATTN_SMEM_BYTES  (ATTN_SMEM_FLOATS * 4)   // 169984 B

__global__ __launch_bounds__(256) void attn_kernel(
    const float* __restrict__ qkv, float* __restrict__ attn,
    float* __restrict__ avg_out)
{
    extern __shared__ float sm[];
    float* Qt = sm + QT_OFF;
    float* Kt = sm + KT_OFF;
    float* Vs = sm + V_OFF;
    float* S  = sm + S_OFF;

    int bh  = blockIdx.x;
    int p   = bh >> 11;
    int rr  = bh & 2047;
    int nid = rr >> 4;
    int h   = rr & 15;
    int t   = threadIdx.x;
    int col = h * HDIM;

    // ---- load Q,K (transposed) and V tiles ----
#pragma unroll
    for (int it = 0; it < 8; ++it) {
        int f  = t + it * 256;          // 0..2047
        int i  = f >> 4;                // row 0..127
        int d0 = (f & 15) << 2;         // 0..60
        int rowoff = ((2 * i + p) * 128 + nid) * QKVDIM;
        float4 q4 = *(const float4*)&qkv[rowoff + col + d0];
        float4 k4 = *(const float4*)&qkv[rowoff + 1024 + col + d0];
        float4 v4 = *(const float4*)&qkv[rowoff + 2048 + col + d0];
        Qt[(d0 + 0) * 132 + i] = q4.x; Qt[(d0 + 1) * 132 + i] = q4.y;
        Qt[(d0 + 2) * 132 + i] = q4.z; Qt[(d0 + 3) * 132 + i] = q4.w;
        Kt[(d0 + 0) * 132 + i] = k4.x; Kt[(d0 + 1) * 132 + i] = k4.y;
        Kt[(d0 + 2) * 132 + i] = k4.z; Kt[(d0 + 3) * 132 + i] = k4.w;
        *(float4*)&Vs[i * 68 + d0] = v4;
    }
    __syncthreads();

    // ---- scores S = Q K^T (q already scaled) : 8x8 per thread, f32x2 ----
    {
        int tm = t >> 4, tn = t & 15;
        unsigned long long acc[8][4];
#pragma unroll
        for (int i = 0; i < 8; ++i)
#pragma unroll
            for (int j = 0; j < 4; ++j) acc[i][j] = 0ull;

        for (int d = 0; d < 64; ++d) {
            float4 fa0 = *(const float4*)&Qt[d * 132 + tm * 8];
            float4 fa1 = *(const float4*)&Qt[d * 132 + tm * 8 + 4];
            ulonglong2 fb0 = *(const ulonglong2*)&Kt[d * 132 + tn * 8];
            ulonglong2 fb1 = *(const ulonglong2*)&Kt[d * 132 + tn * 8 + 4];
            float av[8] = {fa0.x, fa0.y, fa0.z, fa0.w, fa1.x, fa1.y, fa1.z, fa1.w};
#pragma unroll
            for (int i = 0; i < 8; ++i) {
                unsigned long long ap = pack2(av[i], av[i]);
                acc[i][0] = ffma2(ap, fb0.x, acc[i][0]);
                acc[i][1] = ffma2(ap, fb0.y, acc[i][1]);
                acc[i][2] = ffma2(ap, fb1.x, acc[i][2]);
                acc[i][3] = ffma2(ap, fb1.y, acc[i][3]);
            }
        }
#pragma unroll
        for (int i = 0; i < 8; ++i) {
            float2 c0 = unpack2(acc[i][0]);
            float2 c1 = unpack2(acc[i][1]);
            float2 c2 = unpack2(acc[i][2]);
            float2 c3 = unpack2(acc[i][3]);
            float* sp = &S[(tm * 8 + i) * 132 + tn * 8];
            *(float4*)sp       = make_float4(c0.x, c0.y, c1.x, c1.y);
            *(float4*)(sp + 4) = make_float4(c2.x, c2.y, c3.x, c3.y);
        }
    }
    __syncthreads();

    // ---- softmax over rows (keys axis) ----
    if (t < 128) {
        float* srow = &S[t * 132];
        float mx = -1e30f;
        for (int j = 0; j < 128; ++j) mx = fmaxf(mx, srow[j]);
        float sum = 0.f;
        for (int j = 0; j < 128; ++j) {
            float e = __expf(srow[j] - mx);
            srow[j] = e;
            sum += e;
        }
        float inv = 1.0f / sum;
        for (int j = 0; j < 128; ++j) srow[j] *= inv;
    }
    __syncthreads();

    // ---- avg_w: column sums over queries / H ----
    if (t < 128) {
        float s = 0.f;
        for (int i = 0; i < 128; ++i) s += S[i * 132 + t];
        avg_out[bh * 128 + t] = s * 0.0625f;   // / HEADS
    }

    // ---- A·V : 4 rows x 8 cols per thread, f32x2 ----
    {
        int tm2 = t >> 3;    // 0..31 -> rows tm2*4..+3
        int tn2 = t & 7;     // cols tn2*8..+7
        unsigned long long acc[4][4];
#pragma unroll
        for (int i = 0; i < 4; ++i)
#pragma unroll
            for (int j = 0; j < 4; ++j) acc[i][j] = 0ull;

        for (int j = 0; j < 128; ++j) {
            ulonglong2 v01 = *(const ulonglong2*)&Vs[j * 68 + tn2 * 8];
            ulonglong2 v23 = *(const ulonglong2*)&Vs[j * 68 + tn2 * 8 + 4];
#pragma unroll
            for (int i = 0; i < 4; ++i) {
                float wv = S[(tm2 * 4 + i) * 132 + j];
                unsigned long long wp = pack2(wv, wv);
                acc[i][0] = ffma2(wp, v01.x, acc[i][0]);
                acc[i][1] = ffma2(wp, v01.y, acc[i][1]);
                acc[i][2] = ffma2(wp, v23.x, acc[i][2]);
                acc[i][3] = ffma2(wp, v23.y, acc[i][3]);
            }
        }
#pragma unroll
        for (int i = 0; i < 4; ++i) {
            int iq = tm2 * 4 + i;
            float2 c0 = unpack2(acc[i][0]);
            float2 c1 = unpack2(acc[i][1]);
            float2 c2 = unpack2(acc[i][2]);
            float2 c3 = unpack2(acc[i][3]);
            int ob = ((2 * iq + p) * 128 + nid) * EDIM + col + tn2 * 8;
            *(float4*)&attn[ob]     = make_float4(c0.x, c0.y, c1.x, c1.y);
            *(float4*)&attn[ob + 4] = make_float4(c2.x, c2.y, c3.x, c3.y);
        }
    }
}

// ---------------------------------------------------------------------------
// Launch
// ---------------------------------------------------------------------------
extern "C" void kernel_launch(void* const* d_in, const int* in_sizes, int n_in,
                              void* d_out, int out_size)
{
    const float* x    = (const float*)d_in[0];
    const float* ln1w = (const float*)d_in[1];
    const float* ln1b = (const float*)d_in[2];
    const float* inw  = (const float*)d_in[3];
    const float* inb  = (const float*)d_in[4];
    const float* ln2w = (const float*)d_in[5];
    const float* ln2b = (const float*)d_in[6];
    float* out = (float*)d_out;

    float *xn, *qkv, *attn;
    cudaGetSymbolAddress((void**)&xn,   g_xn);
    cudaGetSymbolAddress((void**)&qkv,  g_qkv);
    cudaGetSymbolAddress((void**)&attn, g_attn);

    cudaFuncSetAttribute(attn_kernel,
                         cudaFuncAttributeMaxDynamicSharedMemorySize,
                         ATTN_SMEM_BYTES);

    // 1) xn = LN1(x)
    ln_kernel<<<NROWS, 256>>>(x, nullptr, ln1w, ln1b, xn);
    // 2) qkv = xn @ in_w^T + in_b  (q pre-scaled by 1/8)
    qkv_gemm_kernel<<<dim3(24, 256), 256>>>(xn, inw, inb, qkv);
    // 3) attention + avg_w (second output region of d_out)
    attn_kernel<<<NBH, 256, ATTN_SMEM_BYTES>>>(qkv, attn, out + OUT_ELEMS);
    // 4) out = LN2(xn + attn)
    ln_kernel<<<NROWS, 256>>>(xn, attn, ln2w, ln2b, out);
}

// round 6
// speedup vs baseline: 2.0537x; 2.0537x over previous
#include <cuda_runtime.h>
#include <cuda_bf16.h>
#include <cstdint>

// ---------------------------------------------------------------------------
// Problem constants
// ---------------------------------------------------------------------------
#define EDIM   1024
#define NAQ    128
#define BSZ    256
#define NROWS  (BSZ * NAQ)          // 32768
#define QKVDIM 3072
#define HEADS  16
#define HDIM   64
#define NBH    (BSZ * HEADS)        // 4096 attention batches
#define OUT_ELEMS (NROWS * EDIM)

// ---------------------------------------------------------------------------
// Scratch (device globals: allocation-free)
// ---------------------------------------------------------------------------
__device__ float g_xn  [(size_t)NROWS * EDIM];       // ln1(x) fp32 (residual)
__device__ float g_qkv [(size_t)NROWS * QKVDIM];     // qkv (q scaled)
__device__ float g_attn[(size_t)NROWS * EDIM];       // attention output
__device__ __nv_bfloat16 g_ahi[(size_t)NROWS * EDIM];
__device__ __nv_bfloat16 g_alo[(size_t)NROWS * EDIM];
__device__ __nv_bfloat16 g_whi[(size_t)QKVDIM * EDIM];
__device__ __nv_bfloat16 g_wlo[(size_t)QKVDIM * EDIM];

// ---------------------------------------------------------------------------
// Helpers (portable: no sm_103a-specific instructions — the harness lowers
// through compute_103, which rejects tcgen05/TMEM/arch-specific TMA)
// ---------------------------------------------------------------------------
__device__ __forceinline__ uint32_t smem_u32(const void* p) {
    uint32_t a;
    asm("{ .reg .u64 t; cvta.to.shared.u64 t, %1; cvt.u32.u64 %0, t; }"
        : "=r"(a) : "l"(p));
    return a;
}
__device__ __forceinline__ void cp_async16(uint32_t dst, const void* src) {
    asm volatile("cp.async.cg.shared.global [%0], [%1], 16;"
                 :: "r"(dst), "l"(src) : "memory");
}
#define CP_COMMIT() asm volatile("cp.async.commit_group;" ::: "memory")
#define CP_WAIT_2() asm volatile("cp.async.wait_group 2;" ::: "memory")

__device__ __forceinline__ void ldmx4(uint32_t* r, uint32_t addr) {
    asm volatile("ldmatrix.sync.aligned.m8n8.x4.shared.b16 {%0,%1,%2,%3}, [%4];"
                 : "=r"(r[0]), "=r"(r[1]), "=r"(r[2]), "=r"(r[3]) : "r"(addr));
}
__device__ __forceinline__ void mma_bf16(float* c, const uint32_t* a,
                                         uint32_t b0, uint32_t b1) {
    asm volatile(
        "mma.sync.aligned.m16n8k16.row.col.f32.bf16.bf16.f32 "
        "{%0,%1,%2,%3}, {%4,%5,%6,%7}, {%8,%9}, {%0,%1,%2,%3};"
        : "+f"(c[0]), "+f"(c[1]), "+f"(c[2]), "+f"(c[3])
        : "r"(a[0]), "r"(a[1]), "r"(a[2]), "r"(a[3]), "r"(b0), "r"(b1));
}

// Packed f32x2 helpers (attention kernel)
__device__ __forceinline__ unsigned long long pack2(float lo, float hi) {
    unsigned long long r;
    asm("mov.b64 %0, {%1, %2};"
        : "=l"(r) : "r"(__float_as_uint(lo)), "r"(__float_as_uint(hi)));
    return r;
}
__device__ __forceinline__ float2 unpack2(unsigned long long v) {
    unsigned int lo, hi;
    asm("mov.b64 {%0, %1}, %2;" : "=r"(lo), "=r"(hi) : "l"(v));
    return make_float2(__uint_as_float(lo), __uint_as_float(hi));
}
__device__ __forceinline__ unsigned long long ffma2(
    unsigned long long a, unsigned long long b, unsigned long long c) {
    unsigned long long d;
    asm("fma.rn.f32x2 %0, %1, %2, %3;" : "=l"(d) : "l"(a), "l"(b), "l"(c));
    return d;
}

// bf16 hi/lo split of 4 floats -> two packed uint2
__device__ __forceinline__ void split4(float4 v, uint2& h, uint2& l) {
    __nv_bfloat16 h0 = __float2bfloat16(v.x);
    __nv_bfloat16 h1 = __float2bfloat16(v.y);
    __nv_bfloat16 h2 = __float2bfloat16(v.z);
    __nv_bfloat16 h3 = __float2bfloat16(v.w);
    __nv_bfloat16 l0 = __float2bfloat16(v.x - __bfloat162float(h0));
    __nv_bfloat16 l1 = __float2bfloat16(v.y - __bfloat162float(h1));
    __nv_bfloat16 l2 = __float2bfloat16(v.z - __bfloat162float(h2));
    __nv_bfloat16 l3 = __float2bfloat16(v.w - __bfloat162float(h3));
    h.x = (uint32_t)__bfloat16_as_ushort(h0) | ((uint32_t)__bfloat16_as_ushort(h1) << 16);
    h.y = (uint32_t)__bfloat16_as_ushort(h2) | ((uint32_t)__bfloat16_as_ushort(h3) << 16);
    l.x = (uint32_t)__bfloat16_as_ushort(l0) | ((uint32_t)__bfloat16_as_ushort(l1) << 16);
    l.y = (uint32_t)__bfloat16_as_ushort(l2) | ((uint32_t)__bfloat16_as_ushort(l3) << 16);
}

// ---------------------------------------------------------------------------
// LayerNorm (+ optional residual, + optional bf16 hi/lo split outputs)
// ---------------------------------------------------------------------------
__global__ __launch_bounds__(256) void ln_kernel(
    const float* __restrict__ in, const float* __restrict__ res,
    const float* __restrict__ w, const float* __restrict__ b,
    float* __restrict__ out,
    __nv_bfloat16* __restrict__ hi, __nv_bfloat16* __restrict__ lo)
{
    __shared__ float red_s[8];
    __shared__ float red_q[8];
    size_t row = blockIdx.x;
    int t = threadIdx.x;

    const float4* px = (const float4*)(in + row * EDIM);
    float4 v = px[t];
    if (res != nullptr) {
        const float4* pr = (const float4*)(res + row * EDIM);
        float4 rv = pr[t];
        v.x += rv.x; v.y += rv.y; v.z += rv.z; v.w += rv.w;
    }
    float s = v.x + v.y + v.z + v.w;
    float q = v.x * v.x + v.y * v.y + v.z * v.z + v.w * v.w;
#pragma unroll
    for (int o = 16; o > 0; o >>= 1) {
        s += __shfl_xor_sync(0xffffffffu, s, o);
        q += __shfl_xor_sync(0xffffffffu, q, o);
    }
    if ((t & 31) == 0) { red_s[t >> 5] = s; red_q[t >> 5] = q; }
    __syncthreads();
    float tot = 0.f, totq = 0.f;
#pragma unroll
    for (int k = 0; k < 8; ++k) { tot += red_s[k]; totq += red_q[k]; }

    float mean = tot * (1.0f / EDIM);
    float var  = totq * (1.0f / EDIM) - mean * mean;
    float rstd = rsqrtf(var + 1e-5f);

    int c0 = t * 4;
    float4 wv = *(const float4*)(w + c0);
    float4 bv = *(const float4*)(b + c0);
    float4 o4;
    o4.x = (v.x - mean) * rstd * wv.x + bv.x;
    o4.y = (v.y - mean) * rstd * wv.y + bv.y;
    o4.z = (v.z - mean) * rstd * wv.z + bv.z;
    o4.w = (v.w - mean) * rstd * wv.w + bv.w;
    ((float4*)(out + row * EDIM))[t] = o4;

    if (hi != nullptr) {
        uint2 hp, lp;
        split4(o4, hp, lp);
        *(uint2*)(hi + row * EDIM + c0) = hp;
        *(uint2*)(lo + row * EDIM + c0) = lp;
    }
}

// ---------------------------------------------------------------------------
// Weight split: in_w fp32 -> bf16 hi/lo.  One block per weight row.
// ---------------------------------------------------------------------------
__global__ __launch_bounds__(256) void split_w_kernel(
    const float* __restrict__ w,
    __nv_bfloat16* __restrict__ hi, __nv_bfloat16* __restrict__ lo)
{
    size_t base = (size_t)blockIdx.x * EDIM + threadIdx.x * 4;
    float4 v = *(const float4*)(w + base);
    uint2 hp, lp;
    split4(v, hp, lp);
    *(uint2*)(hi + base) = hp;
    *(uint2*)(lo + base) = lp;
}

// ---------------------------------------------------------------------------
// QKV GEMM via mma.sync (HMMA bf16, split-precision 3-pass):
//   C[m,n] = (sum_k A[m,k]*W[n,k] + bias[n]) * (n < 1024 ? 0.125 : 1)
// CTA tile 128x128, BK=32, 4-stage cp.async pipeline, 8 warps (2x4),
// warp tile 64x32. SMEM rows padded to 40 bf16 (80B) -> ldmatrix conflict-free.
// ---------------------------------------------------------------------------
#define BK        32
#define ROWPAD    40                       // bf16 elements per SMEM row
#define SUB_BYTES (128 * ROWPAD * 2)       // 10240 per 128x32 bf16 sub-tile
#define STAGE_BYTES (4 * SUB_BYTES)        // 40960: Ahi, Alo, Whi, Wlo
#define NSTAGES   4
#define GSMEM_BYTES (NSTAGES * STAGE_BYTES)  // 163840

__global__ __launch_bounds__(256, 1) void qkv_gemm_mma_kernel(
    const __nv_bfloat16* __restrict__ ahi, const __nv_bfloat16* __restrict__ alo,
    const __nv_bfloat16* __restrict__ whi, const __nv_bfloat16* __restrict__ wlo,
    const float* __restrict__ bias, float* __restrict__ C)
{
    extern __shared__ char smem[];
    uint32_t sb = smem_u32(smem);
    int tid  = threadIdx.x;
    int lane = tid & 31;
    int wid  = tid >> 5;
    int wm   = wid >> 2;          // 0..1
    int wn   = wid & 3;           // 0..3
    int bn = blockIdx.x;          // 0..23
    int bm = blockIdx.y;          // 0..255

    const __nv_bfloat16* bases[4] = {
        ahi + (size_t)bm * 128 * EDIM,
        alo + (size_t)bm * 128 * EDIM,
        whi + (size_t)bn * 128 * EDIM,
        wlo + (size_t)bn * 128 * EDIM
    };

    // ---- stage loader: 2048 x 16B granules, 8 per thread ----
    auto load_stage = [&](int c, int s) {
        uint32_t base = sb + s * STAGE_BYTES;
        int kbase = c * BK;
#pragma unroll
        for (int i = 0; i < 8; ++i) {
            int g   = tid + i * 256;        // 0..2047
            int sub = g >> 9;               // 0..3
            int idx = g & 511;
            int r   = idx >> 2;             // 0..127
            int kk  = idx & 3;              // 0..3 (granule of 8 bf16)
            uint32_t dst = base + sub * SUB_BYTES + r * (ROWPAD * 2) + kk * 16;
            const __nv_bfloat16* src = bases[sub] + (size_t)r * EDIM + kbase + kk * 8;
            cp_async16(dst, src);
        }
    };

    // prologue: 3 stages in flight
    load_stage(0, 0); CP_COMMIT();
    load_stage(1, 1); CP_COMMIT();
    load_stage(2, 2); CP_COMMIT();

    float acc[4][4][4];
#pragma unroll
    for (int i = 0; i < 4; ++i)
#pragma unroll
        for (int j = 0; j < 4; ++j)
#pragma unroll
            for (int k = 0; k < 4; ++k) acc[i][j][k] = 0.f;

    // fragment address components (byte offsets within a sub-tile)
    int a_row = wm * 64 + (lane & 15);
    int a_col = (lane >> 4) * 8;
    int b_row = wn * 32 + ((lane >> 4) << 3) + (lane & 7);
    int b_col = ((lane >> 3) & 1) * 8;

    for (int c = 0; c < 32; ++c) {
        int s = c & 3;
        uint32_t stage = sb + s * STAGE_BYTES;
        CP_WAIT_2();
        __syncthreads();

        uint32_t sAhi = stage;
        uint32_t sAlo = stage + SUB_BYTES;
        uint32_t sWhi = stage + 2 * SUB_BYTES;
        uint32_t sWlo = stage + 3 * SUB_BYTES;

#pragma unroll
        for (int ks = 0; ks < BK; ks += 16) {
            uint32_t fahi[4][4], falo[4][4];
            uint32_t fbhi[2][4], fblo[2][4];
#pragma unroll
            for (int mt = 0; mt < 4; ++mt) {
                uint32_t off = (a_row + mt * 16) * (ROWPAD * 2) + (ks + a_col) * 2;
                ldmx4(fahi[mt], sAhi + off);
                ldmx4(falo[mt], sAlo + off);
            }
#pragma unroll
            for (int np = 0; np < 2; ++np) {
                uint32_t off = (b_row + np * 16) * (ROWPAD * 2) + (ks + b_col) * 2;
                ldmx4(fbhi[np], sWhi + off);
                ldmx4(fblo[np], sWlo + off);
            }
#pragma unroll
            for (int mt = 0; mt < 4; ++mt) {
#pragma unroll
                for (int nt = 0; nt < 4; ++nt) {
                    int np = nt >> 1, h = (nt & 1) * 2;
                    mma_bf16(acc[mt][nt], fahi[mt], fbhi[np][h], fbhi[np][h + 1]);
                    mma_bf16(acc[mt][nt], fahi[mt], fblo[np][h], fblo[np][h + 1]);
                    mma_bf16(acc[mt][nt], falo[mt], fbhi[np][h], fbhi[np][h + 1]);
                }
            }
        }

        if (c + 3 < 32) load_stage(c + 3, (c + 3) & 3);
        CP_COMMIT();
    }

    // ---- epilogue: direct register -> global stores, bias + q-scale fused ----
    int q  = lane >> 2;           // 0..7
    int tc = (lane & 3) * 2;
    float scale = (bn < 8) ? 0.125f : 1.0f;
#pragma unroll
    for (int mt = 0; mt < 4; ++mt) {
#pragma unroll
        for (int nt = 0; nt < 4; ++nt) {
            int row = bm * 128 + wm * 64 + mt * 16 + q;
            int col = bn * 128 + wn * 32 + nt * 8 + tc;
            float b0 = bias[col], b1 = bias[col + 1];
            float2 o0 = make_float2((acc[mt][nt][0] + b0) * scale,
                                    (acc[mt][nt][1] + b1) * scale);
            float2 o1 = make_float2((acc[mt][nt][2] + b0) * scale,
                                    (acc[mt][nt][3] + b1) * scale);
            *(float2*)(C + (size_t)row * QKVDIM + col)       = o0;
            *(float2*)(C + (size_t)(row + 8) * QKVDIM + col) = o1;
        }
    }
}

// ---------------------------------------------------------------------------
// Attention: one block per bh in [0,4096).  (unchanged from R4 passing kernel)
// ---------------------------------------------------------------------------
#define QT_OFF 0
#define KT_OFF (64 * 132)
#define V_OFF  (2 * 64 * 132)
#define S_OFF  (V_OFF + 128 * 68)
#define ATTN_SMEM_FLOATS (S_OFF + 128 * 132)
#define ATTN_SMEM_BYTES  (ATTN_SMEM_FLOATS * 4)

__global__ __launch_bounds__(256) void attn_kernel(
    const float* __restrict__ qkv, float* __restrict__ attn,
    float* __restrict__ avg_out)
{
    extern __shared__ float sm[];
    float* Qt = sm + QT_OFF;
    float* Kt = sm + KT_OFF;
    float* Vs = sm + V_OFF;
    float* S  = sm + S_OFF;

    int bh  = blockIdx.x;
    int p   = bh >> 11;
    int rr  = bh & 2047;
    int nid = rr >> 4;
    int h   = rr & 15;
    int t   = threadIdx.x;
    int col = h * HDIM;

#pragma unroll
    for (int it = 0; it < 8; ++it) {
        int f  = t + it * 256;
        int i  = f >> 4;
        int d0 = (f & 15) << 2;
        int rowoff = ((2 * i + p) * 128 + nid) * QKVDIM;
        float4 q4 = *(const float4*)&qkv[rowoff + col + d0];
        float4 k4 = *(const float4*)&qkv[rowoff + 1024 + col + d0];
        float4 v4 = *(const float4*)&qkv[rowoff + 2048 + col + d0];
        Qt[(d0 + 0) * 132 + i] = q4.x; Qt[(d0 + 1) * 132 + i] = q4.y;
        Qt[(d0 + 2) * 132 + i] = q4.z; Qt[(d0 + 3) * 132 + i] = q4.w;
        Kt[(d0 + 0) * 132 + i] = k4.x; Kt[(d0 + 1) * 132 + i] = k4.y;
        Kt[(d0 + 2) * 132 + i] = k4.z; Kt[(d0 + 3) * 132 + i] = k4.w;
        *(float4*)&Vs[i * 68 + d0] = v4;
    }
    __syncthreads();

    {
        int tm = t >> 4, tn = t & 15;
        unsigned long long acc[8][4];
#pragma unroll
        for (int i = 0; i < 8; ++i)
#pragma unroll
            for (int j = 0; j < 4; ++j) acc[i][j] = 0ull;

        for (int d = 0; d < 64; ++d) {
            float4 fa0 = *(const float4*)&Qt[d * 132 + tm * 8];
            float4 fa1 = *(const float4*)&Qt[d * 132 + tm * 8 + 4];
            ulonglong2 fb0 = *(const ulonglong2*)&Kt[d * 132 + tn * 8];
            ulonglong2 fb1 = *(const ulonglong2*)&Kt[d * 132 + tn * 8 + 4];
            float av[8] = {fa0.x, fa0.y, fa0.z, fa0.w, fa1.x, fa1.y, fa1.z, fa1.w};
#pragma unroll
            for (int i = 0; i < 8; ++i) {
                unsigned long long ap = pack2(av[i], av[i]);
                acc[i][0] = ffma2(ap, fb0.x, acc[i][0]);
                acc[i][1] = ffma2(ap, fb0.y, acc[i][1]);
                acc[i][2] = ffma2(ap, fb1.x, acc[i][2]);
                acc[i][3] = ffma2(ap, fb1.y, acc[i][3]);
            }
        }
#pragma unroll
        for (int i = 0; i < 8; ++i) {
            float2 c0 = unpack2(acc[i][0]);
            float2 c1 = unpack2(acc[i][1]);
            float2 c2 = unpack2(acc[i][2]);
            float2 c3 = unpack2(acc[i][3]);
            float* sp = &S[(tm * 8 + i) * 132 + tn * 8];
            *(float4*)sp       = make_float4(c0.x, c0.y, c1.x, c1.y);
            *(float4*)(sp + 4) = make_float4(c2.x, c2.y, c3.x, c3.y);
        }
    }
    __syncthreads();

    if (t < 128) {
        float* srow = &S[t * 132];
        float mx = -1e30f;
        for (int j = 0; j < 128; ++j) mx = fmaxf(mx, srow[j]);
        float sum = 0.f;
        for (int j = 0; j < 128; ++j) {
            float e = __expf(srow[j] - mx);
            srow[j] = e;
            sum += e;
        }
        float inv = 1.0f / sum;
        for (int j = 0; j < 128; ++j) srow[j] *= inv;
    }
    __syncthreads();

    if (t < 128) {
        float s = 0.f;
        for (int i = 0; i < 128; ++i) s += S[i * 132 + t];
        avg_out[bh * 128 + t] = s * 0.0625f;
    }

    {
        int tm2 = t >> 3;
        int tn2 = t & 7;
        unsigned long long acc[4][4];
#pragma unroll
        for (int i = 0; i < 4; ++i)
#pragma unroll
            for (int j = 0; j < 4; ++j) acc[i][j] = 0ull;

        for (int j = 0; j < 128; ++j) {
            ulonglong2 v01 = *(const ulonglong2*)&Vs[j * 68 + tn2 * 8];
            ulonglong2 v23 = *(const ulonglong2*)&Vs[j * 68 + tn2 * 8 + 4];
#pragma unroll
            for (int i = 0; i < 4; ++i) {
                float wv = S[(tm2 * 4 + i) * 132 + j];
                unsigned long long wp = pack2(wv, wv);
                acc[i][0] = ffma2(wp, v01.x, acc[i][0]);
                acc[i][1] = ffma2(wp, v01.y, acc[i][1]);
                acc[i][2] = ffma2(wp, v23.x, acc[i][2]);
                acc[i][3] = ffma2(wp, v23.y, acc[i][3]);
            }
        }
#pragma unroll
        for (int i = 0; i < 4; ++i) {
            int iq = tm2 * 4 + i;
            float2 c0 = unpack2(acc[i][0]);
            float2 c1 = unpack2(acc[i][1]);
            float2 c2 = unpack2(acc[i][2]);
            float2 c3 = unpack2(acc[i][3]);
            int ob = ((2 * iq + p) * 128 + nid) * EDIM + col + tn2 * 8;
            *(float4*)&attn[ob]     = make_float4(c0.x, c0.y, c1.x, c1.y);
            *(float4*)&attn[ob + 4] = make_float4(c2.x, c2.y, c3.x, c3.y);
        }
    }
}

// ---------------------------------------------------------------------------
// Launch
// ---------------------------------------------------------------------------
extern "C" void kernel_launch(void* const* d_in, const int* in_sizes, int n_in,
                              void* d_out, int out_size)
{
    const float* x    = (const float*)d_in[0];
    const float* ln1w = (const float*)d_in[1];
    const float* ln1b = (const float*)d_in[2];
    const float* inw  = (const float*)d_in[3];
    const float* inb  = (const float*)d_in[4];
    const float* ln2w = (const float*)d_in[5];
    const float* ln2b = (const float*)d_in[6];
    float* out = (float*)d_out;

    float *xn, *qkv, *attn;
    __nv_bfloat16 *ahi, *alo, *whi, *wlo;
    cudaGetSymbolAddress((void**)&xn,   g_xn);
    cudaGetSymbolAddress((void**)&qkv,  g_qkv);
    cudaGetSymbolAddress((void**)&attn, g_attn);
    cudaGetSymbolAddress((void**)&ahi,  g_ahi);
    cudaGetSymbolAddress((void**)&alo,  g_alo);
    cudaGetSymbolAddress((void**)&whi,  g_whi);
    cudaGetSymbolAddress((void**)&wlo,  g_wlo);

    cudaFuncSetAttribute(attn_kernel,
                         cudaFuncAttributeMaxDynamicSharedMemorySize,
                         ATTN_SMEM_BYTES);
    cudaFuncSetAttribute(qkv_gemm_mma_kernel,
                         cudaFuncAttributeMaxDynamicSharedMemorySize,
                         GSMEM_BYTES);

    // 1) xn = LN1(x), fused bf16 hi/lo split
    ln_kernel<<<NROWS, 256>>>(x, nullptr, ln1w, ln1b, xn, ahi, alo);
    // 2) weight split (bf16 hi/lo)
    split_w_kernel<<<QKVDIM, 256>>>(inw, whi, wlo);
    // 3) HMMA QKV GEMM (bias + q-scale fused)
    qkv_gemm_mma_kernel<<<dim3(24, 256), 256, GSMEM_BYTES>>>(
        ahi, alo, whi, wlo, inb, qkv);
    // 4) attention + avg_w
    attn_kernel<<<NBH, 256, ATTN_SMEM_BYTES>>>(qkv, attn, out + OUT_ELEMS);
    // 5) out = LN2(xn + attn)
    ln_kernel<<<NROWS, 256>>>(xn, attn, ln2w, ln2b, out, nullptr, nullptr);
}

// round 7
// speedup vs baseline: 2.0572x; 1.0017x over previous
#include <cuda_runtime.h>
#include <cuda_bf16.h>
#include <cstdint>

// ---------------------------------------------------------------------------
// Problem constants
// ---------------------------------------------------------------------------
#define EDIM   1024
#define NAQ    128
#define BSZ    256
#define NROWS  (BSZ * NAQ)          // 32768
#define QKVDIM 3072
#define HEADS  16
#define HDIM   64
#define NBH    (BSZ * HEADS)        // 4096 attention batches
#define OUT_ELEMS (NROWS * EDIM)

// ---------------------------------------------------------------------------
// Scratch (device globals: allocation-free)
// ---------------------------------------------------------------------------
__device__ float g_xn  [(size_t)NROWS * EDIM];       // ln1(x) fp32 (residual)
__device__ float g_qkv [(size_t)NROWS * QKVDIM];     // qkv (q scaled)
__device__ float g_attn[(size_t)NROWS * EDIM];       // attention output
__device__ __nv_bfloat16 g_ahi[(size_t)NROWS * EDIM];
__device__ __nv_bfloat16 g_alo[(size_t)NROWS * EDIM];
__device__ __nv_bfloat16 g_whi[(size_t)QKVDIM * EDIM];
__device__ __nv_bfloat16 g_wlo[(size_t)QKVDIM * EDIM];

// ---------------------------------------------------------------------------
// Helpers (portable subset only: harness lowers through compute_103)
// ---------------------------------------------------------------------------
__device__ __forceinline__ uint32_t smem_u32(const void* p) {
    uint32_t a;
    asm("{ .reg .u64 t; cvta.to.shared.u64 t, %1; cvt.u32.u64 %0, t; }"
        : "=r"(a) : "l"(p));
    return a;
}
__device__ __forceinline__ void cp_async16(uint32_t dst, const void* src) {
    asm volatile("cp.async.cg.shared.global [%0], [%1], 16;"
                 :: "r"(dst), "l"(src) : "memory");
}
#define CP_COMMIT() asm volatile("cp.async.commit_group;" ::: "memory")
#define CP_WAIT_1() asm volatile("cp.async.wait_group 1;" ::: "memory")

__device__ __forceinline__ void ldmx4(uint32_t* r, uint32_t addr) {
    asm volatile("ldmatrix.sync.aligned.m8n8.x4.shared.b16 {%0,%1,%2,%3}, [%4];"
                 : "=r"(r[0]), "=r"(r[1]), "=r"(r[2]), "=r"(r[3]) : "r"(addr));
}
__device__ __forceinline__ void mma_bf16(float* c, const uint32_t* a,
                                         uint32_t b0, uint32_t b1) {
    asm volatile(
        "mma.sync.aligned.m16n8k16.row.col.f32.bf16.bf16.f32 "
        "{%0,%1,%2,%3}, {%4,%5,%6,%7}, {%8,%9}, {%0,%1,%2,%3};"
        : "+f"(c[0]), "+f"(c[1]), "+f"(c[2]), "+f"(c[3])
        : "r"(a[0]), "r"(a[1]), "r"(a[2]), "r"(a[3]), "r"(b0), "r"(b1));
}

// bf16 hi/lo split of 4 floats -> two packed uint2
__device__ __forceinline__ void split4(float4 v, uint2& h, uint2& l) {
    __nv_bfloat16 h0 = __float2bfloat16(v.x);
    __nv_bfloat16 h1 = __float2bfloat16(v.y);
    __nv_bfloat16 h2 = __float2bfloat16(v.z);
    __nv_bfloat16 h3 = __float2bfloat16(v.w);
    __nv_bfloat16 l0 = __float2bfloat16(v.x - __bfloat162float(h0));
    __nv_bfloat16 l1 = __float2bfloat16(v.y - __bfloat162float(h1));
    __nv_bfloat16 l2 = __float2bfloat16(v.z - __bfloat162float(h2));
    __nv_bfloat16 l3 = __float2bfloat16(v.w - __bfloat162float(h3));
    h.x = (uint32_t)__bfloat16_as_ushort(h0) | ((uint32_t)__bfloat16_as_ushort(h1) << 16);
    h.y = (uint32_t)__bfloat16_as_ushort(h2) | ((uint32_t)__bfloat16_as_ushort(h3) << 16);
    l.x = (uint32_t)__bfloat16_as_ushort(l0) | ((uint32_t)__bfloat16_as_ushort(l1) << 16);
    l.y = (uint32_t)__bfloat16_as_ushort(l2) | ((uint32_t)__bfloat16_as_ushort(l3) << 16);
}

// ---------------------------------------------------------------------------
// LayerNorm (+ optional residual, + optional bf16 hi/lo split outputs)
// ---------------------------------------------------------------------------
__global__ __launch_bounds__(256) void ln_kernel(
    const float* __restrict__ in, const float* __restrict__ res,
    const float* __restrict__ w, const float* __restrict__ b,
    float* __restrict__ out,
    __nv_bfloat16* __restrict__ hi, __nv_bfloat16* __restrict__ lo)
{
    __shared__ float red_s[8];
    __shared__ float red_q[8];
    size_t row = blockIdx.x;
    int t = threadIdx.x;

    const float4* px = (const float4*)(in + row * EDIM);
    float4 v = px[t];
    if (res != nullptr) {
        const float4* pr = (const float4*)(res + row * EDIM);
        float4 rv = pr[t];
        v.x += rv.x; v.y += rv.y; v.z += rv.z; v.w += rv.w;
    }
    float s = v.x + v.y + v.z + v.w;
    float q = v.x * v.x + v.y * v.y + v.z * v.z + v.w * v.w;
#pragma unroll
    for (int o = 16; o > 0; o >>= 1) {
        s += __shfl_xor_sync(0xffffffffu, s, o);
        q += __shfl_xor_sync(0xffffffffu, q, o);
    }
    if ((t & 31) == 0) { red_s[t >> 5] = s; red_q[t >> 5] = q; }
    __syncthreads();
    float tot = 0.f, totq = 0.f;
#pragma unroll
    for (int k = 0; k < 8; ++k) { tot += red_s[k]; totq += red_q[k]; }

    float mean = tot * (1.0f / EDIM);
    float var  = totq * (1.0f / EDIM) - mean * mean;
    float rstd = rsqrtf(var + 1e-5f);

    int c0 = t * 4;
    float4 wv = *(const float4*)(w + c0);
    float4 bv = *(const float4*)(b + c0);
    float4 o4;
    o4.x = (v.x - mean) * rstd * wv.x + bv.x;
    o4.y = (v.y - mean) * rstd * wv.y + bv.y;
    o4.z = (v.z - mean) * rstd * wv.z + bv.z;
    o4.w = (v.w - mean) * rstd * wv.w + bv.w;
    ((float4*)(out + row * EDIM))[t] = o4;

    if (hi != nullptr) {
        uint2 hp, lp;
        split4(o4, hp, lp);
        *(uint2*)(hi + row * EDIM + c0) = hp;
        *(uint2*)(lo + row * EDIM + c0) = lp;
    }
}

// ---------------------------------------------------------------------------
// Weight split: in_w fp32 -> bf16 hi/lo.
// ---------------------------------------------------------------------------
__global__ __launch_bounds__(256) void split_w_kernel(
    const float* __restrict__ w,
    __nv_bfloat16* __restrict__ hi, __nv_bfloat16* __restrict__ lo)
{
    size_t base = (size_t)blockIdx.x * EDIM + threadIdx.x * 4;
    float4 v = *(const float4*)(w + base);
    uint2 hp, lp;
    split4(v, hp, lp);
    *(uint2*)(hi + base) = hp;
    *(uint2*)(lo + base) = lp;
}

// ---------------------------------------------------------------------------
// QKV GEMM via mma.sync (HMMA bf16, split-precision 3-pass):
// CTA tile 128(M) x 256(N), BK=32, 512 threads (16 warps, 2x8),
// warp tile 64x32, 3-stage cp.async pipeline. Rows padded to 40 bf16 (80B).
// ---------------------------------------------------------------------------
#define BK        32
#define ROWB      80                        // bytes per SMEM row (40 bf16)
#define A_SUB     (128 * ROWB)              // 10240
#define B_SUB     (256 * ROWB)              // 20480
#define STAGE_BYTES (2 * A_SUB + 2 * B_SUB) // 61440: Ahi, Alo, Whi, Wlo
#define NSTAGES   3
#define GSMEM_BYTES (NSTAGES * STAGE_BYTES) // 184320

__global__ __launch_bounds__(512, 1) void qkv_gemm_mma_kernel(
    const __nv_bfloat16* __restrict__ ahi, const __nv_bfloat16* __restrict__ alo,
    const __nv_bfloat16* __restrict__ whi, const __nv_bfloat16* __restrict__ wlo,
    const float* __restrict__ bias, float* __restrict__ C)
{
    extern __shared__ char smem[];
    uint32_t sb = smem_u32(smem);
    int tid  = threadIdx.x;
    int lane = tid & 31;
    int wid  = tid >> 5;          // 0..15
    int wm   = wid >> 3;          // 0..1
    int wn   = wid & 7;           // 0..7
    int bn = blockIdx.x;          // 0..11 (256 cols each)
    int bm = blockIdx.y;          // 0..255

    auto load_stage = [&](int c, int s) {
        uint32_t base = sb + s * STAGE_BYTES;
        int kbase = c * BK;
        {   // Ahi: 512 granules
            int r = tid >> 2, kk = tid & 3;
            cp_async16(base + r * ROWB + kk * 16,
                       ahi + (size_t)(bm * 128 + r) * EDIM + kbase + kk * 8);
        }
        {   // Alo
            int r = tid >> 2, kk = tid & 3;
            cp_async16(base + A_SUB + r * ROWB + kk * 16,
                       alo + (size_t)(bm * 128 + r) * EDIM + kbase + kk * 8);
        }
#pragma unroll
        for (int i = 0; i < 2; ++i) {   // Whi: 1024 granules
            int g = tid + i * 512;
            int r = g >> 2, kk = g & 3;
            cp_async16(base + 2 * A_SUB + r * ROWB + kk * 16,
                       whi + (size_t)(bn * 256 + r) * EDIM + kbase + kk * 8);
        }
#pragma unroll
        for (int i = 0; i < 2; ++i) {   // Wlo
            int g = tid + i * 512;
            int r = g >> 2, kk = g & 3;
            cp_async16(base + 2 * A_SUB + B_SUB + r * ROWB + kk * 16,
                       wlo + (size_t)(bn * 256 + r) * EDIM + kbase + kk * 8);
        }
    };

    load_stage(0, 0); CP_COMMIT();
    load_stage(1, 1); CP_COMMIT();

    float acc[4][4][4];
#pragma unroll
    for (int i = 0; i < 4; ++i)
#pragma unroll
        for (int j = 0; j < 4; ++j)
#pragma unroll
            for (int k = 0; k < 4; ++k) acc[i][j][k] = 0.f;

    int a_row = wm * 64 + (lane & 15);
    int a_col = (lane >> 4) * 8;
    int b_row = wn * 32 + ((lane >> 4) << 3) + (lane & 7);
    int b_col = ((lane >> 3) & 1) * 8;

    for (int c = 0; c < 32; ++c) {
        int s = c - (c / 3) * 3;            // c % 3
        uint32_t stage = sb + s * STAGE_BYTES;
        CP_WAIT_1();
        __syncthreads();

        uint32_t sAhi = stage;
        uint32_t sAlo = stage + A_SUB;
        uint32_t sWhi = stage + 2 * A_SUB;
        uint32_t sWlo = stage + 2 * A_SUB + B_SUB;

#pragma unroll
        for (int ks = 0; ks < BK; ks += 16) {
            uint32_t fahi[4][4], falo[4][4];
            uint32_t fbhi[2][4], fblo[2][4];
#pragma unroll
            for (int mt = 0; mt < 4; ++mt) {
                uint32_t off = (a_row + mt * 16) * ROWB + (ks + a_col) * 2;
                ldmx4(fahi[mt], sAhi + off);
                ldmx4(falo[mt], sAlo + off);
            }
#pragma unroll
            for (int np = 0; np < 2; ++np) {
                uint32_t off = (b_row + np * 16) * ROWB + (ks + b_col) * 2;
                ldmx4(fbhi[np], sWhi + off);
                ldmx4(fblo[np], sWlo + off);
            }
#pragma unroll
            for (int mt = 0; mt < 4; ++mt) {
#pragma unroll
                for (int nt = 0; nt < 4; ++nt) {
                    int np = nt >> 1, h = (nt & 1) * 2;
                    mma_bf16(acc[mt][nt], fahi[mt], fbhi[np][h], fbhi[np][h + 1]);
                    mma_bf16(acc[mt][nt], fahi[mt], fblo[np][h], fblo[np][h + 1]);
                    mma_bf16(acc[mt][nt], falo[mt], fbhi[np][h], fbhi[np][h + 1]);
                }
            }
        }
        __syncthreads();
        if (c + 2 < 32) {
            int s2 = (c + 2) - ((c + 2) / 3) * 3;
            load_stage(c + 2, s2);
        }
        CP_COMMIT();
    }

    // epilogue: bias + q-scale fused, direct register stores
    int qr = lane >> 2;
    int tc = (lane & 3) * 2;
    float scale = (bn < 4) ? 0.125f : 1.0f;
#pragma unroll
    for (int mt = 0; mt < 4; ++mt) {
#pragma unroll
        for (int nt = 0; nt < 4; ++nt) {
            int row = bm * 128 + wm * 64 + mt * 16 + qr;
            int col = bn * 256 + wn * 32 + nt * 8 + tc;
            float b0 = bias[col], b1 = bias[col + 1];
            float2 o0 = make_float2((acc[mt][nt][0] + b0) * scale,
                                    (acc[mt][nt][1] + b1) * scale);
            float2 o1 = make_float2((acc[mt][nt][2] + b0) * scale,
                                    (acc[mt][nt][3] + b1) * scale);
            *(float2*)(C + (size_t)row * QKVDIM + col)       = o0;
            *(float2*)(C + (size_t)(row + 8) * QKVDIM + col) = o1;
        }
    }
}

// ---------------------------------------------------------------------------
// Attention via HMMA split-bf16: one block (256 thr) per bh in [0,4096).
// SMEM (bytes): Qhi 0, Qlo 18432, Khi 36864, Klo 55296 (128x72 bf16 each),
//   Vthi 73728, Vtlo 91136 (64x136 bf16, transposed), S 108544 (128x132 f32).
// P hi/lo reuse the Q/K regions after softmax.
// ---------------------------------------------------------------------------
#define AQ_ROWB 144                     // 72 bf16
#define AV_ROWB 272                     // 136 bf16
#define QHI_B 0
#define QLO_B 18432
#define KHI_B 36864
#define KLO_B 55296
#define VTHI_B 73728
#define VTLO_B 91136
#define S_B    108544
#define S_F    (S_B / 4)
#define PHI_B  0
#define PLO_B  36864
#define ATTN_SMEM_BYTES (S_B + 128 * 132 * 4)   // 176128

__global__ __launch_bounds__(256, 1) void attn_kernel(
    const float* __restrict__ qkv, float* __restrict__ attn,
    float* __restrict__ avg_out)
{
    extern __shared__ char smem[];
    uint32_t sb = smem_u32(smem);
    float* S = (float*)(smem + S_B);

    int bh  = blockIdx.x;
    int p   = bh >> 11;
    int rr  = bh & 2047;
    int nid = rr >> 4;
    int h   = rr & 15;
    int t   = threadIdx.x;
    int lane = t & 31;
    int wid  = t >> 5;            // 0..7
    int wm   = wid >> 2;          // 0..1
    int wn   = wid & 3;           // 0..3
    int col = h * HDIM;

    // ---- load q,k,v fp32; split to bf16 hi/lo in SMEM (V transposed) ----
#pragma unroll
    for (int it = 0; it < 8; ++it) {
        int f  = t + it * 256;          // 0..2047
        int i  = f >> 4;                // row 0..127
        int d0 = (f & 15) << 2;         // 0..60
        int rowoff = ((2 * i + p) * 128 + nid) * QKVDIM;
        float4 q4 = *(const float4*)&qkv[rowoff + col + d0];
        float4 k4 = *(const float4*)&qkv[rowoff + 1024 + col + d0];
        float4 v4 = *(const float4*)&qkv[rowoff + 2048 + col + d0];
        uint2 hp, lp;
        split4(q4, hp, lp);
        *(uint2*)(smem + QHI_B + i * AQ_ROWB + d0 * 2) = hp;
        *(uint2*)(smem + QLO_B + i * AQ_ROWB + d0 * 2) = lp;
        split4(k4, hp, lp);
        *(uint2*)(smem + KHI_B + i * AQ_ROWB + d0 * 2) = hp;
        *(uint2*)(smem + KLO_B + i * AQ_ROWB + d0 * 2) = lp;
        // V transposed scatter
        float vv[4] = {v4.x, v4.y, v4.z, v4.w};
#pragma unroll
        for (int j = 0; j < 4; ++j) {
            __nv_bfloat16 vh = __float2bfloat16(vv[j]);
            __nv_bfloat16 vl = __float2bfloat16(vv[j] - __bfloat162float(vh));
            *(__nv_bfloat16*)(smem + VTHI_B + (d0 + j) * AV_ROWB + i * 2) = vh;
            *(__nv_bfloat16*)(smem + VTLO_B + (d0 + j) * AV_ROWB + i * 2) = vl;
        }
    }
    __syncthreads();

    int a_row = wm * 64 + (lane & 15);
    int a_col = (lane >> 4) * 8;
    int b_row = wn * 32 + ((lane >> 4) << 3) + (lane & 7);
    int b_col = ((lane >> 3) & 1) * 8;

    // ---- scores S = Q K^T (3-pass split-bf16 HMMA), warp tile 64x32 ----
    {
        float acc[4][4][4];
#pragma unroll
        for (int i = 0; i < 4; ++i)
#pragma unroll
            for (int j = 0; j < 4; ++j)
#pragma unroll
                for (int k = 0; k < 4; ++k) acc[i][j][k] = 0.f;

#pragma unroll
        for (int ks = 0; ks < 64; ks += 16) {
            uint32_t fahi[4][4], falo[4][4];
            uint32_t fbhi[2][4], fblo[2][4];
#pragma unroll
            for (int mt = 0; mt < 4; ++mt) {
                uint32_t off = (a_row + mt * 16) * AQ_ROWB + (ks + a_col) * 2;
                ldmx4(fahi[mt], sb + QHI_B + off);
                ldmx4(falo[mt], sb + QLO_B + off);
            }
#pragma unroll
            for (int np = 0; np < 2; ++np) {
                uint32_t off = (b_row + np * 16) * AQ_ROWB + (ks + b_col) * 2;
                ldmx4(fbhi[np], sb + KHI_B + off);
                ldmx4(fblo[np], sb + KLO_B + off);
            }
#pragma unroll
            for (int mt = 0; mt < 4; ++mt) {
#pragma unroll
                for (int nt = 0; nt < 4; ++nt) {
                    int np = nt >> 1, hh = (nt & 1) * 2;
                    mma_bf16(acc[mt][nt], fahi[mt], fbhi[np][hh], fbhi[np][hh + 1]);
                    mma_bf16(acc[mt][nt], fahi[mt], fblo[np][hh], fblo[np][hh + 1]);
                    mma_bf16(acc[mt][nt], falo[mt], fbhi[np][hh], fbhi[np][hh + 1]);
                }
            }
        }
        int qr = lane >> 2, tc = (lane & 3) * 2;
#pragma unroll
        for (int mt = 0; mt < 4; ++mt) {
#pragma unroll
            for (int nt = 0; nt < 4; ++nt) {
                int row = wm * 64 + mt * 16 + qr;
                int cc  = wn * 32 + nt * 8 + tc;
                S[row * 132 + cc]           = acc[mt][nt][0];
                S[row * 132 + cc + 1]       = acc[mt][nt][1];
                S[(row + 8) * 132 + cc]     = acc[mt][nt][2];
                S[(row + 8) * 132 + cc + 1] = acc[mt][nt][3];
            }
        }
    }
    __syncthreads();

    // ---- softmax: warp-parallel, 16 rows per warp, lane-parallel cols ----
    {
#pragma unroll
        for (int r8 = 0; r8 < 16; ++r8) {
            int row = wid * 16 + r8;
            float4 v = *(float4*)&S[row * 132 + lane * 4];
            float mx = fmaxf(fmaxf(v.x, v.y), fmaxf(v.z, v.w));
#pragma unroll
            for (int o = 16; o > 0; o >>= 1)
                mx = fmaxf(mx, __shfl_xor_sync(0xffffffffu, mx, o));
            v.x = __expf(v.x - mx); v.y = __expf(v.y - mx);
            v.z = __expf(v.z - mx); v.w = __expf(v.w - mx);
            float sum = v.x + v.y + v.z + v.w;
#pragma unroll
            for (int o = 16; o > 0; o >>= 1)
                sum += __shfl_xor_sync(0xffffffffu, sum, o);
            float inv = 1.0f / sum;
            v.x *= inv; v.y *= inv; v.z *= inv; v.w *= inv;
            *(float4*)&S[row * 132 + lane * 4] = v;
        }
    }
    __syncthreads();

    // ---- avg_w (column sums / H) + split P into bf16 hi/lo (reuse Q/K) ----
    if (t < 128) {
        float s = 0.f;
        for (int i = 0; i < 128; ++i) s += S[i * 132 + t];
        avg_out[bh * 128 + t] = s * 0.0625f;
    }
#pragma unroll
    for (int i = 0; i < 16; ++i) {
        int g = t + i * 256;            // 0..4095 float4 groups
        int row = g >> 5;
        int c0  = (g & 31) << 2;
        float4 v = *(float4*)&S[row * 132 + c0];
        uint2 hp, lp;
        split4(v, hp, lp);
        *(uint2*)(smem + PHI_B + row * AV_ROWB + c0 * 2) = hp;
        *(uint2*)(smem + PLO_B + row * AV_ROWB + c0 * 2) = lp;
    }
    __syncthreads();

    // ---- A·V (3-pass split-bf16 HMMA), warp tile 64x16, K=128 ----
    {
        int b_rowv = wn * 16 + ((lane >> 4) << 3) + (lane & 7);
        float acc[4][2][4];
#pragma unroll
        for (int i = 0; i < 4; ++i)
#pragma unroll
            for (int j = 0; j < 2; ++j)
#pragma unroll
                for (int k = 0; k < 4; ++k) acc[i][j][k] = 0.f;

#pragma unroll
        for (int ks = 0; ks < 128; ks += 16) {
            uint32_t fahi[4][4], falo[4][4];
            uint32_t fbhi[4], fblo[4];
#pragma unroll
            for (int mt = 0; mt < 4; ++mt) {
                uint32_t off = (a_row + mt * 16) * AV_ROWB + (ks + a_col) * 2;
                ldmx4(fahi[mt], sb + PHI_B + off);
                ldmx4(falo[mt], sb + PLO_B + off);
            }
            {
                uint32_t off = b_rowv * AV_ROWB + (ks + b_col) * 2;
                ldmx4(fbhi, sb + VTHI_B + off);
                ldmx4(fblo, sb + VTLO_B + off);
            }
#pragma unroll
            for (int mt = 0; mt < 4; ++mt) {
#pragma unroll
                for (int nt = 0; nt < 2; ++nt) {
                    int hh = nt * 2;
                    mma_bf16(acc[mt][nt], fahi[mt], fbhi[hh], fbhi[hh + 1]);
                    mma_bf16(acc[mt][nt], fahi[mt], fblo[hh], fblo[hh + 1]);
                    mma_bf16(acc[mt][nt], falo[mt], fbhi[hh], fbhi[hh + 1]);
                }
            }
        }
        // epilogue: scatter through the inverse head-reshape
        int qr = lane >> 2, tc = (lane & 3) * 2;
#pragma unroll
        for (int mt = 0; mt < 4; ++mt) {
#pragma unroll
            for (int nt = 0; nt < 2; ++nt) {
                int row = wm * 64 + mt * 16 + qr;           // query index
                int cc  = wn * 16 + nt * 8 + tc;            // head-dim col
                int ob0 = ((2 * row + p) * 128 + nid) * EDIM + col + cc;
                int ob1 = ((2 * (row + 8) + p) * 128 + nid) * EDIM + col + cc;
                *(float2*)&attn[ob0] = make_float2(acc[mt][nt][0], acc[mt][nt][1]);
                *(float2*)&attn[ob1] = make_float2(acc[mt][nt][2], acc[mt][nt][3]);
            }
        }
    }
}

// ---------------------------------------------------------------------------
// Launch
// ---------------------------------------------------------------------------
extern "C" void kernel_launch(void* const* d_in, const int* in_sizes, int n_in,
                              void* d_out, int out_size)
{
    const float* x    = (const float*)d_in[0];
    const float* ln1w = (const float*)d_in[1];
    const float* ln1b = (const float*)d_in[2];
    const float* inw  = (const float*)d_in[3];
    const float* inb  = (const float*)d_in[4];
    const float* ln2w = (const float*)d_in[5];
    const float* ln2b = (const float*)d_in[6];
    float* out = (float*)d_out;

    float *xn, *qkv, *attn;
    __nv_bfloat16 *ahi, *alo, *whi, *wlo;
    cudaGetSymbolAddress((void**)&xn,   g_xn);
    cudaGetSymbolAddress((void**)&qkv,  g_qkv);
    cudaGetSymbolAddress((void**)&attn, g_attn);
    cudaGetSymbolAddress((void**)&ahi,  g_ahi);
    cudaGetSymbolAddress((void**)&alo,  g_alo);
    cudaGetSymbolAddress((void**)&whi,  g_whi);
    cudaGetSymbolAddress((void**)&wlo,  g_wlo);

    cudaFuncSetAttribute(attn_kernel,
                         cudaFuncAttributeMaxDynamicSharedMemorySize,
                         ATTN_SMEM_BYTES);
    cudaFuncSetAttribute(qkv_gemm_mma_kernel,
                         cudaFuncAttributeMaxDynamicSharedMemorySize,
                         GSMEM_BYTES);

    // 1) xn = LN1(x), fused bf16 hi/lo split
    ln_kernel<<<NROWS, 256>>>(x, nullptr, ln1w, ln1b, xn, ahi, alo);
    // 2) weight split (bf16 hi/lo)
    split_w_kernel<<<QKVDIM, 256>>>(inw, whi, wlo);
    // 3) HMMA QKV GEMM, 128x256 tile, 512 threads
    qkv_gemm_mma_kernel<<<dim3(12, 256), 512, GSMEM_BYTES>>>(
        ahi, alo, whi, wlo, inb, qkv);
    // 4) HMMA attention + avg_w
    attn_kernel<<<NBH, 256, ATTN_SMEM_BYTES>>>(qkv, attn, out + OUT_ELEMS);
    // 5) out = LN2(xn + attn)
    ln_kernel<<<NROWS, 256>>>(xn, attn, ln2w, ln2b, out, nullptr, nullptr);
}

// round 8
// speedup vs baseline: 2.7583x; 1.3408x over previous
#include <cuda_runtime.h>
#include <cstdint>

// ---------------------------------------------------------------------------
// Problem constants
// ---------------------------------------------------------------------------
#define EDIM   1024
#define NAQ    128
#define BSZ    256
#define NROWS  (BSZ * NAQ)          // 32768
#define QKVDIM 3072
#define HEADS  16
#define HDIM   64
#define NBH    (BSZ * HEADS)        // 4096 attention batches
#define OUT_ELEMS (NROWS * EDIM)

// ---------------------------------------------------------------------------
// Scratch (device globals: allocation-free)
// ---------------------------------------------------------------------------
__device__ float g_xn  [(size_t)NROWS * EDIM];       // ln1(x) fp32
__device__ float g_qkv [(size_t)NROWS * QKVDIM];     // qkv (q scaled)
__device__ float g_attn[(size_t)NROWS * EDIM];       // attention output

// ---------------------------------------------------------------------------
// Helpers (portable subset: harness lowers through compute_103)
// ---------------------------------------------------------------------------
__device__ __forceinline__ uint32_t smem_u32(const void* p) {
    uint32_t a;
    asm("{ .reg .u64 t; cvta.to.shared.u64 t, %1; cvt.u32.u64 %0, t; }"
        : "=r"(a) : "l"(p));
    return a;
}
__device__ __forceinline__ void cp_async16(uint32_t dst, const void* src) {
    asm volatile("cp.async.cg.shared.global [%0], [%1], 16;"
                 :: "r"(dst), "l"(src) : "memory");
}
#define CP_COMMIT() asm volatile("cp.async.commit_group;" ::: "memory")

__device__ __forceinline__ uint32_t f2tf(float f) {
    uint32_t r;
    asm("cvt.rna.tf32.f32 %0, %1;" : "=r"(r) : "f"(f));
    return r;
}
__device__ __forceinline__ void mma_tf32(float* c, const uint32_t* a,
                                         uint32_t b0, uint32_t b1) {
    asm volatile(
        "mma.sync.aligned.m16n8k8.row.col.f32.tf32.tf32.f32 "
        "{%0,%1,%2,%3}, {%4,%5,%6,%7}, {%8,%9}, {%0,%1,%2,%3};"
        : "+f"(c[0]), "+f"(c[1]), "+f"(c[2]), "+f"(c[3])
        : "r"(a[0]), "r"(a[1]), "r"(a[2]), "r"(a[3]), "r"(b0), "r"(b1));
}

// ---------------------------------------------------------------------------
// LayerNorm (+ optional residual)
// ---------------------------------------------------------------------------
__global__ __launch_bounds__(256) void ln_kernel(
    const float* __restrict__ in, const float* __restrict__ res,
    const float* __restrict__ w, const float* __restrict__ b,
    float* __restrict__ out)
{
    __shared__ float red_s[8];
    __shared__ float red_q[8];
    size_t row = blockIdx.x;
    int t = threadIdx.x;

    const float4* px = (const float4*)(in + row * EDIM);
    float4 v = px[t];
    if (res != nullptr) {
        const float4* pr = (const float4*)(res + row * EDIM);
        float4 rv = pr[t];
        v.x += rv.x; v.y += rv.y; v.z += rv.z; v.w += rv.w;
    }
    float s = v.x + v.y + v.z + v.w;
    float q = v.x * v.x + v.y * v.y + v.z * v.z + v.w * v.w;
#pragma unroll
    for (int o = 16; o > 0; o >>= 1) {
        s += __shfl_xor_sync(0xffffffffu, s, o);
        q += __shfl_xor_sync(0xffffffffu, q, o);
    }
    if ((t & 31) == 0) { red_s[t >> 5] = s; red_q[t >> 5] = q; }
    __syncthreads();
    float tot = 0.f, totq = 0.f;
#pragma unroll
    for (int k = 0; k < 8; ++k) { tot += red_s[k]; totq += red_q[k]; }

    float mean = tot * (1.0f / EDIM);
    float var  = totq * (1.0f / EDIM) - mean * mean;
    float rstd = rsqrtf(var + 1e-5f);

    int c0 = t * 4;
    float4 wv = *(const float4*)(w + c0);
    float4 bv = *(const float4*)(b + c0);
    float4 o4;
    o4.x = (v.x - mean) * rstd * wv.x + bv.x;
    o4.y = (v.y - mean) * rstd * wv.y + bv.y;
    o4.z = (v.z - mean) * rstd * wv.z + bv.z;
    o4.w = (v.w - mean) * rstd * wv.w + bv.w;
    ((float4*)(out + row * EDIM))[t] = o4;
}

// ---------------------------------------------------------------------------
// QKV GEMM via TF32 mma.sync (single pass):
//   C[m,n] = (sum_k A[m,k]*W[n,k] + bias[n]) * (n < 1024 ? 0.125 : 1)
// CTA tile 128(M) x 256(N), BK=32, 256 threads (8 warps 2x4),
// warp tile 64x64, 4-stage cp.async pipeline, one __syncthreads/iter.
// SMEM rows padded to 36 floats (144B) -> conflict-free scalar LDS.
// ---------------------------------------------------------------------------
#define GS_BK    32
#define GS_ROWF  36
#define GS_A_SUB (128 * GS_ROWF * 4)       // 18432
#define GS_B_SUB (256 * GS_ROWF * 4)       // 36864
#define GS_STAGE (GS_A_SUB + GS_B_SUB)     // 55296
#define GS_SMEM  (4 * GS_STAGE)            // 221184

__global__ __launch_bounds__(256, 1) void qkv_gemm_tf32_kernel(
    const float* __restrict__ A, const float* __restrict__ W,
    const float* __restrict__ bias, float* __restrict__ C)
{
    extern __shared__ char smem[];
    uint32_t sb = smem_u32(smem);
    int tid  = threadIdx.x;
    int lane = tid & 31;
    int wid  = tid >> 5;          // 0..7
    int wm   = wid >> 2;          // 0..1
    int wn   = wid & 3;           // 0..3
    int bn = blockIdx.x;          // 0..11 (256 cols each)
    int bm = blockIdx.y;          // 0..255

    auto load_stage = [&](int c, int s) {
        uint32_t base = sb + s * GS_STAGE;
        int kbase = c * GS_BK;
#pragma unroll
        for (int i = 0; i < 4; ++i) {     // A: 1024 granules
            int g = tid + i * 256;
            int r = g >> 3, kk = g & 7;
            cp_async16(base + r * 144 + kk * 16,
                       A + (size_t)(bm * 128 + r) * EDIM + kbase + kk * 4);
        }
#pragma unroll
        for (int i = 0; i < 8; ++i) {     // W: 2048 granules
            int g = tid + i * 256;
            int r = g >> 3, kk = g & 7;
            cp_async16(base + GS_A_SUB + r * 144 + kk * 16,
                       W + (size_t)(bn * 256 + r) * EDIM + kbase + kk * 4);
        }
    };

    load_stage(0, 0); CP_COMMIT();
    load_stage(1, 1); CP_COMMIT();
    load_stage(2, 2); CP_COMMIT();

    float acc[4][8][4];
#pragma unroll
    for (int i = 0; i < 4; ++i)
#pragma unroll
        for (int j = 0; j < 8; ++j)
#pragma unroll
            for (int k = 0; k < 4; ++k) acc[i][j][k] = 0.f;

    int fr = lane >> 2;           // fragment row / B n-offset
    int fc = lane & 3;            // fragment col (k)

    for (int c = 0; c < 32; ++c) {
        asm volatile("cp.async.wait_group 2;" ::: "memory");
        __syncthreads();
        const float* As = (const float*)(smem + (c & 3) * GS_STAGE);
        const float* Bs = (const float*)(smem + (c & 3) * GS_STAGE + GS_A_SUB);

#pragma unroll
        for (int ks = 0; ks < GS_BK; ks += 8) {
            uint32_t fa[4][4], fb[8][2];
#pragma unroll
            for (int mt = 0; mt < 4; ++mt) {
                int ar = wm * 64 + mt * 16 + fr;
                fa[mt][0] = f2tf(As[ar * 36 + ks + fc]);
                fa[mt][1] = f2tf(As[(ar + 8) * 36 + ks + fc]);
                fa[mt][2] = f2tf(As[ar * 36 + ks + fc + 4]);
                fa[mt][3] = f2tf(As[(ar + 8) * 36 + ks + fc + 4]);
            }
#pragma unroll
            for (int nt = 0; nt < 8; ++nt) {
                int nb = wn * 64 + nt * 8 + fr;
                fb[nt][0] = f2tf(Bs[nb * 36 + ks + fc]);
                fb[nt][1] = f2tf(Bs[nb * 36 + ks + fc + 4]);
            }
#pragma unroll
            for (int mt = 0; mt < 4; ++mt)
#pragma unroll
                for (int nt = 0; nt < 8; ++nt)
                    mma_tf32(acc[mt][nt], fa[mt], fb[nt][0], fb[nt][1]);
        }

        if (c + 3 < 32) load_stage(c + 3, (c + 3) & 3);
        CP_COMMIT();
    }

    // epilogue: bias + q-scale fused, direct register stores
    int qr = lane >> 2;
    int tc = (lane & 3) * 2;
    float scale = (bn < 4) ? 0.125f : 1.0f;   // q * HD^-0.5
#pragma unroll
    for (int mt = 0; mt < 4; ++mt) {
#pragma unroll
        for (int nt = 0; nt < 8; ++nt) {
            int row = bm * 128 + wm * 64 + mt * 16 + qr;
            int col = bn * 256 + wn * 64 + nt * 8 + tc;
            float b0 = bias[col], b1 = bias[col + 1];
            float2 o0 = make_float2((acc[mt][nt][0] + b0) * scale,
                                    (acc[mt][nt][1] + b1) * scale);
            float2 o1 = make_float2((acc[mt][nt][2] + b0) * scale,
                                    (acc[mt][nt][3] + b1) * scale);
            *(float2*)(C + (size_t)row * QKVDIM + col)       = o0;
            *(float2*)(C + (size_t)(row + 8) * QKVDIM + col) = o1;
        }
    }
}

// ---------------------------------------------------------------------------
// Attention via TF32 mma.sync: one block (256 thr) per bh in [0,4096).
//   bh = (b%2)*2048 + n*16 + h ; sequence index i -> original batch 2i+p.
// SMEM (floats): Qs 128x68, Ks 128x68, Vs 128x72 (row-major), S 128x132.
// S (fp32) is consumed directly as the TF32 A operand of A*V.
// ---------------------------------------------------------------------------
#define AT_Q_F 0
#define AT_K_F (128 * 68)
#define AT_V_F (2 * 128 * 68)
#define AT_S_F (AT_V_F + 128 * 72)
#define ATTN_SMEM_BYTES ((AT_S_F + 128 * 132) * 4)   // 174080

__global__ __launch_bounds__(256, 1) void attn_kernel(
    const float* __restrict__ qkv, float* __restrict__ attn,
    float* __restrict__ avg_out)
{
    extern __shared__ float sm[];
    float* Qs = sm + AT_Q_F;
    float* Ks = sm + AT_K_F;
    float* Vs = sm + AT_V_F;
    float* S  = sm + AT_S_F;

    int bh  = blockIdx.x;
    int p   = bh >> 11;
    int rr  = bh & 2047;
    int nid = rr >> 4;
    int h   = rr & 15;
    int t   = threadIdx.x;
    int lane = t & 31;
    int wid  = t >> 5;            // 0..7
    int wm   = wid >> 2;          // 0..1
    int wn   = wid & 3;           // 0..3
    int col = h * HDIM;

    // ---- load Q, K, V tiles (fp32, coalesced gather) ----
#pragma unroll
    for (int it = 0; it < 8; ++it) {
        int f  = t + it * 256;          // 0..2047
        int i  = f >> 4;                // row 0..127
        int d0 = (f & 15) << 2;         // 0..60
        int rowoff = ((2 * i + p) * 128 + nid) * QKVDIM;
        float4 q4 = *(const float4*)&qkv[rowoff + col + d0];
        float4 k4 = *(const float4*)&qkv[rowoff + 1024 + col + d0];
        float4 v4 = *(const float4*)&qkv[rowoff + 2048 + col + d0];
        *(float4*)&Qs[i * 68 + d0] = q4;
        *(float4*)&Ks[i * 68 + d0] = k4;
        *(float4*)&Vs[i * 72 + d0] = v4;
    }
    __syncthreads();

    int fr = lane >> 2;
    int fc = lane & 3;

    // ---- scores S = Q K^T (TF32), warp tile 64x32, K=64 ----
    {
        float acc[4][4][4];
#pragma unroll
        for (int i = 0; i < 4; ++i)
#pragma unroll
            for (int j = 0; j < 4; ++j)
#pragma unroll
                for (int k = 0; k < 4; ++k) acc[i][j][k] = 0.f;

#pragma unroll
        for (int ks = 0; ks < 64; ks += 8) {
            uint32_t fa[4][4], fb[4][2];
#pragma unroll
            for (int mt = 0; mt < 4; ++mt) {
                int ar = wm * 64 + mt * 16 + fr;
                fa[mt][0] = f2tf(Qs[ar * 68 + ks + fc]);
                fa[mt][1] = f2tf(Qs[(ar + 8) * 68 + ks + fc]);
                fa[mt][2] = f2tf(Qs[ar * 68 + ks + fc + 4]);
                fa[mt][3] = f2tf(Qs[(ar + 8) * 68 + ks + fc + 4]);
            }
#pragma unroll
            for (int nt = 0; nt < 4; ++nt) {
                int nb = wn * 32 + nt * 8 + fr;
                fb[nt][0] = f2tf(Ks[nb * 68 + ks + fc]);
                fb[nt][1] = f2tf(Ks[nb * 68 + ks + fc + 4]);
            }
#pragma unroll
            for (int mt = 0; mt < 4; ++mt)
#pragma unroll
                for (int nt = 0; nt < 4; ++nt)
                    mma_tf32(acc[mt][nt], fa[mt], fb[nt][0], fb[nt][1]);
        }
        int qr = lane >> 2, tc = (lane & 3) * 2;
#pragma unroll
        for (int mt = 0; mt < 4; ++mt) {
#pragma unroll
            for (int nt = 0; nt < 4; ++nt) {
                int row = wm * 64 + mt * 16 + qr;
                int cc  = wn * 32 + nt * 8 + tc;
                S[row * 132 + cc]           = acc[mt][nt][0];
                S[row * 132 + cc + 1]       = acc[mt][nt][1];
                S[(row + 8) * 132 + cc]     = acc[mt][nt][2];
                S[(row + 8) * 132 + cc + 1] = acc[mt][nt][3];
            }
        }
    }
    __syncthreads();

    // ---- softmax: 16 rows per warp, lane-parallel columns ----
#pragma unroll
    for (int r8 = 0; r8 < 16; ++r8) {
        int row = wid * 16 + r8;
        float4 v = *(float4*)&S[row * 132 + lane * 4];
        float mx = fmaxf(fmaxf(v.x, v.y), fmaxf(v.z, v.w));
#pragma unroll
        for (int o = 16; o > 0; o >>= 1)
            mx = fmaxf(mx, __shfl_xor_sync(0xffffffffu, mx, o));
        v.x = __expf(v.x - mx); v.y = __expf(v.y - mx);
        v.z = __expf(v.z - mx); v.w = __expf(v.w - mx);
        float sum = v.x + v.y + v.z + v.w;
#pragma unroll
        for (int o = 16; o > 0; o >>= 1)
            sum += __shfl_xor_sync(0xffffffffu, sum, o);
        float inv = 1.0f / sum;
        v.x *= inv; v.y *= inv; v.z *= inv; v.w *= inv;
        *(float4*)&S[row * 132 + lane * 4] = v;
    }
    __syncthreads();

    // ---- avg_w: column sums over queries / H ----
    if (t < 128) {
        float s = 0.f;
        for (int i = 0; i < 128; ++i) s += S[i * 132 + t];
        avg_out[bh * 128 + t] = s * 0.0625f;
    }

    // ---- A·V (TF32): A = S directly, warp tile 64x16, K=128 ----
    {
        float acc[4][2][4];
#pragma unroll
        for (int i = 0; i < 4; ++i)
#pragma unroll
            for (int j = 0; j < 2; ++j)
#pragma unroll
                for (int k = 0; k < 4; ++k) acc[i][j][k] = 0.f;

#pragma unroll
        for (int ks = 0; ks < 128; ks += 8) {
            uint32_t fa[4][4], fb[2][2];
#pragma unroll
            for (int mt = 0; mt < 4; ++mt) {
                int ar = wm * 64 + mt * 16 + fr;
                fa[mt][0] = f2tf(S[ar * 132 + ks + fc]);
                fa[mt][1] = f2tf(S[(ar + 8) * 132 + ks + fc]);
                fa[mt][2] = f2tf(S[ar * 132 + ks + fc + 4]);
                fa[mt][3] = f2tf(S[(ar + 8) * 132 + ks + fc + 4]);
            }
#pragma unroll
            for (int nt = 0; nt < 2; ++nt) {
                int nb = wn * 16 + nt * 8 + fr;
                fb[nt][0] = f2tf(Vs[(ks + fc) * 72 + nb]);
                fb[nt][1] = f2tf(Vs[(ks + fc + 4) * 72 + nb]);
            }
#pragma unroll
            for (int mt = 0; mt < 4; ++mt)
#pragma unroll
                for (int nt = 0; nt < 2; ++nt)
                    mma_tf32(acc[mt][nt], fa[mt], fb[nt][0], fb[nt][1]);
        }

        // epilogue: scatter through the inverse head-reshape
        int qr = lane >> 2, tc = (lane & 3) * 2;
#pragma unroll
        for (int mt = 0; mt < 4; ++mt) {
#pragma unroll
            for (int nt = 0; nt < 2; ++nt) {
                int row = wm * 64 + mt * 16 + qr;           // query index
                int cc  = wn * 16 + nt * 8 + tc;            // head-dim col
                int ob0 = ((2 * row + p) * 128 + nid) * EDIM + col + cc;
                int ob1 = ((2 * (row + 8) + p) * 128 + nid) * EDIM + col + cc;
                *(float2*)&attn[ob0] = make_float2(acc[mt][nt][0], acc[mt][nt][1]);
                *(float2*)&attn[ob1] = make_float2(acc[mt][nt][2], acc[mt][nt][3]);
            }
        }
    }
}

// ---------------------------------------------------------------------------
// Launch
// ---------------------------------------------------------------------------
extern "C" void kernel_launch(void* const* d_in, const int* in_sizes, int n_in,
                              void* d_out, int out_size)
{
    const float* x    = (const float*)d_in[0];
    const float* ln1w = (const float*)d_in[1];
    const float* ln1b = (const float*)d_in[2];
    const float* inw  = (const float*)d_in[3];
    const float* inb  = (const float*)d_in[4];
    const float* ln2w = (const float*)d_in[5];
    const float* ln2b = (const float*)d_in[6];
    float* out = (float*)d_out;

    float *xn, *qkv, *attn;
    cudaGetSymbolAddress((void**)&xn,   g_xn);
    cudaGetSymbolAddress((void**)&qkv,  g_qkv);
    cudaGetSymbolAddress((void**)&attn, g_attn);

    cudaFuncSetAttribute(attn_kernel,
                         cudaFuncAttributeMaxDynamicSharedMemorySize,
                         ATTN_SMEM_BYTES);
    cudaFuncSetAttribute(qkv_gemm_tf32_kernel,
                         cudaFuncAttributeMaxDynamicSharedMemorySize,
                         GS_SMEM);

    // 1) xn = LN1(x)
    ln_kernel<<<NROWS, 256>>>(x, nullptr, ln1w, ln1b, xn);
    // 2) TF32 QKV GEMM (bias + q-scale fused), reads xn/in_w fp32 directly
    qkv_gemm_tf32_kernel<<<dim3(12, 256), 256, GS_SMEM>>>(xn, inw, inb, qkv);
    // 3) TF32 attention + avg_w
    attn_kernel<<<NBH, 256, ATTN_SMEM_BYTES>>>(qkv, attn, out + OUT_ELEMS);
    // 4) out = LN2(xn + attn)
    ln_kernel<<<NROWS, 256>>>(xn, attn, ln2w, ln2b, out);
}

// round 9
// speedup vs baseline: 3.3157x; 1.2021x over previous
#include <cuda_runtime.h>
#include <cstdint>

// ---------------------------------------------------------------------------
// Problem constants
// ---------------------------------------------------------------------------
#define EDIM   1024
#define NAQ    128
#define BSZ    256
#define NROWS  (BSZ * NAQ)          // 32768
#define QKVDIM 3072
#define HEADS  16
#define HDIM   64
#define NBH    (BSZ * HEADS)        // 4096 attention batches
#define OUT_ELEMS (NROWS * EDIM)

// ---------------------------------------------------------------------------
// Scratch (device globals: allocation-free)
// ---------------------------------------------------------------------------
__device__ float g_xn  [(size_t)NROWS * EDIM];       // ln1(x), tf32-rounded
__device__ float g_qkv [(size_t)NROWS * QKVDIM];     // qkv (q scaled), tf32-rounded
__device__ float g_attn[(size_t)NROWS * EDIM];       // attention output
__device__ float g_wtf [(size_t)QKVDIM * EDIM];      // in_w, fragment-permuted tf32

// ---------------------------------------------------------------------------
// Helpers (portable subset: harness lowers through compute_103)
// ---------------------------------------------------------------------------
__device__ __forceinline__ uint32_t smem_u32(const void* p) {
    uint32_t a;
    asm("{ .reg .u64 t; cvta.to.shared.u64 t, %1; cvt.u32.u64 %0, t; }"
        : "=r"(a) : "l"(p));
    return a;
}
__device__ __forceinline__ void cp_async16(uint32_t dst, const void* src) {
    asm volatile("cp.async.cg.shared.global [%0], [%1], 16;"
                 :: "r"(dst), "l"(src) : "memory");
}
#define CP_COMMIT() asm volatile("cp.async.commit_group;" ::: "memory")

__device__ __forceinline__ uint32_t f2tf(float f) {
    uint32_t r;
    asm("cvt.rna.tf32.f32 %0, %1;" : "=r"(r) : "f"(f));
    return r;
}
__device__ __forceinline__ float roundtf(float f) {
    return __uint_as_float(f2tf(f));
}
__device__ __forceinline__ void mma_tf32(float* c, const uint32_t* a,
                                         uint32_t b0, uint32_t b1) {
    asm volatile(
        "mma.sync.aligned.m16n8k8.row.col.f32.tf32.tf32.f32 "
        "{%0,%1,%2,%3}, {%4,%5,%6,%7}, {%8,%9}, {%0,%1,%2,%3};"
        : "+f"(c[0]), "+f"(c[1]), "+f"(c[2]), "+f"(c[3])
        : "r"(a[0]), "r"(a[1]), "r"(a[2]), "r"(a[3]), "r"(b0), "r"(b1));
}

// ---------------------------------------------------------------------------
// LayerNorm (+ optional residual, optional tf32 rounding of output)
// ---------------------------------------------------------------------------
__global__ __launch_bounds__(256) void ln_kernel(
    const float* __restrict__ in, const float* __restrict__ res,
    const float* __restrict__ w, const float* __restrict__ b,
    float* __restrict__ out, int rnd)
{
    __shared__ float red_s[8];
    __shared__ float red_q[8];
    size_t row = blockIdx.x;
    int t = threadIdx.x;

    const float4* px = (const float4*)(in + row * EDIM);
    float4 v = px[t];
    if (res != nullptr) {
        const float4* pr = (const float4*)(res + row * EDIM);
        float4 rv = pr[t];
        v.x += rv.x; v.y += rv.y; v.z += rv.z; v.w += rv.w;
    }
    float s = v.x + v.y + v.z + v.w;
    float q = v.x * v.x + v.y * v.y + v.z * v.z + v.w * v.w;
#pragma unroll
    for (int o = 16; o > 0; o >>= 1) {
        s += __shfl_xor_sync(0xffffffffu, s, o);
        q += __shfl_xor_sync(0xffffffffu, q, o);
    }
    if ((t & 31) == 0) { red_s[t >> 5] = s; red_q[t >> 5] = q; }
    __syncthreads();
    float tot = 0.f, totq = 0.f;
#pragma unroll
    for (int k = 0; k < 8; ++k) { tot += red_s[k]; totq += red_q[k]; }

    float mean = tot * (1.0f / EDIM);
    float var  = totq * (1.0f / EDIM) - mean * mean;
    float rstd = rsqrtf(var + 1e-5f);

    int c0 = t * 4;
    float4 wv = *(const float4*)(w + c0);
    float4 bv = *(const float4*)(b + c0);
    float4 o4;
    o4.x = (v.x - mean) * rstd * wv.x + bv.x;
    o4.y = (v.y - mean) * rstd * wv.y + bv.y;
    o4.z = (v.z - mean) * rstd * wv.z + bv.z;
    o4.w = (v.w - mean) * rstd * wv.w + bv.w;
    if (rnd) {
        o4.x = roundtf(o4.x); o4.y = roundtf(o4.y);
        o4.z = roundtf(o4.z); o4.w = roundtf(o4.w);
    }
    ((float4*)(out + row * EDIM))[t] = o4;
}

// ---------------------------------------------------------------------------
// Weight permute: in_w (3072x1024 row-major fp32) -> B-fragment order, tf32.
// Output layout: [nb 0..383][kb 0..127][lane 0..31][2]
//   val = { W[8nb+fr][8kb+fc], W[8nb+fr][8kb+fc+4] },  fr=lane>>2, fc=lane&3
// One block = 16 W rows (2 nb), smem-staged, fully coalesced in and out.
// ---------------------------------------------------------------------------
#define PW_SMEM (16 * 1028 * 4)     // 65792 bytes

__global__ __launch_bounds__(256) void permute_w_kernel(
    const float* __restrict__ w, float* __restrict__ wp)
{
    extern __shared__ float s[];
    int blk = blockIdx.x;           // 0..191
    int t = threadIdx.x;
#pragma unroll
    for (int rr = 0; rr < 16; ++rr) {
        float4 v = *(const float4*)(w + (size_t)(blk * 16 + rr) * EDIM + t * 4);
        *(float4*)&s[rr * 1028 + t * 4] = v;
    }
    __syncthreads();
#pragma unroll
    for (int it = 0; it < 32; ++it) {
        int o2 = t + it * 256;              // 0..8191
        int nb_l = o2 >> 12;                // 0..1
        int kb   = (o2 >> 5) & 127;
        int lane = o2 & 31;
        int fr = lane >> 2, fc = lane & 3;
        int rl = nb_l * 8 + fr;
        float2 o;
        o.x = roundtf(s[rl * 1028 + kb * 8 + fc]);
        o.y = roundtf(s[rl * 1028 + kb * 8 + fc + 4]);
        *(float2*)(wp + (((size_t)(blk * 2 + nb_l) * 128 + kb) * 32 + lane) * 2) = o;
    }
}

// ---------------------------------------------------------------------------
// QKV GEMM via TF32 mma.sync (inputs pre-rounded; zero cvt in loop):
//   C[m,n] = (sum_k A[m,k]*W[n,k] + bias[n]) * (n < 1024 ? 0.125 : 1), rounded
// CTA tile 128(M) x 256(N), BK=32, 512 threads (16 warps 2x8),
// warp tile 64x32, 4-stage cp.async pipeline.
// SMEM stage: A row-major padded 36f (18432B) + W fragment-blocks (32768B).
// ---------------------------------------------------------------------------
#define GS_A_BYTES 18432
#define GS_B_BYTES 32768
#define GS_STAGE   (GS_A_BYTES + GS_B_BYTES)   // 51200
#define GS_SMEM    (4 * GS_STAGE)              // 204800

__global__ __launch_bounds__(512, 1) void qkv_gemm_tf32_kernel(
    const float* __restrict__ A, const float* __restrict__ Wp,
    const float* __restrict__ bias, float* __restrict__ C)
{
    extern __shared__ char smem[];
    uint32_t sb = smem_u32(smem);
    int tid  = threadIdx.x;
    int lane = tid & 31;
    int wid  = tid >> 5;          // 0..15
    int wm   = wid >> 3;          // 0..1
    int wn   = wid & 7;           // 0..7
    int bn = blockIdx.x;          // 0..11
    int bm = blockIdx.y;          // 0..255

    auto load_stage = [&](int c, int s) {
        uint32_t base = sb + s * GS_STAGE;
        int kbase = c * 32;
#pragma unroll
        for (int i = 0; i < 2; ++i) {      // A: 1024 granules
            int g = tid + i * 512;
            int r = g >> 3, kk = g & 7;
            cp_async16(base + r * 144 + kk * 16,
                       A + (size_t)(bm * 128 + r) * EDIM + kbase + kk * 4);
        }
#pragma unroll
        for (int i = 0; i < 4; ++i) {      // W: 2048 granules (permuted blocks)
            int g = tid + i * 512;
            int nb = g >> 6, kb = (g >> 4) & 3, pr = g & 15;
            cp_async16(base + GS_A_BYTES + g * 16,
                       Wp + ((size_t)(bn * 32 + nb) * 128 + c * 4 + kb) * 64 + pr * 4);
        }
    };

    load_stage(0, 0); CP_COMMIT();
    load_stage(1, 1); CP_COMMIT();
    load_stage(2, 2); CP_COMMIT();

    float acc[4][4][4];
#pragma unroll
    for (int i = 0; i < 4; ++i)
#pragma unroll
        for (int j = 0; j < 4; ++j)
#pragma unroll
            for (int k = 0; k < 4; ++k) acc[i][j][k] = 0.f;

    int fr = lane >> 2;
    int fc = lane & 3;

    for (int c = 0; c < 32; ++c) {
        asm volatile("cp.async.wait_group 2;" ::: "memory");
        __syncthreads();
        int s = c & 3;
        const float* As = (const float*)(smem + s * GS_STAGE);
        const char*  Bp = smem + s * GS_STAGE + GS_A_BYTES;

#pragma unroll
        for (int ks = 0; ks < 32; ks += 8) {
            int kb = ks >> 3;
            uint32_t fa[4][4];
            uint2 fb[4];
#pragma unroll
            for (int mt = 0; mt < 4; ++mt) {
                int ar = wm * 64 + mt * 16 + fr;
                fa[mt][0] = __float_as_uint(As[ar * 36 + ks + fc]);
                fa[mt][1] = __float_as_uint(As[(ar + 8) * 36 + ks + fc]);
                fa[mt][2] = __float_as_uint(As[ar * 36 + ks + fc + 4]);
                fa[mt][3] = __float_as_uint(As[(ar + 8) * 36 + ks + fc + 4]);
            }
#pragma unroll
            for (int nt = 0; nt < 4; ++nt) {
                int nbl = wn * 4 + nt;
                fb[nt] = *(const uint2*)(Bp + (nbl * 4 + kb) * 256 + lane * 8);
            }
#pragma unroll
            for (int mt = 0; mt < 4; ++mt)
#pragma unroll
                for (int nt = 0; nt < 4; ++nt)
                    mma_tf32(acc[mt][nt], fa[mt], fb[nt].x, fb[nt].y);
        }

        if (c + 3 < 32) load_stage(c + 3, (c + 3) & 3);
        CP_COMMIT();
    }

    // epilogue: bias + q-scale fused, tf32-rounded stores
    int qr = lane >> 2;
    int tc = (lane & 3) * 2;
    float scale = (bn < 4) ? 0.125f : 1.0f;   // q * HD^-0.5
#pragma unroll
    for (int mt = 0; mt < 4; ++mt) {
#pragma unroll
        for (int nt = 0; nt < 4; ++nt) {
            int row = bm * 128 + wm * 64 + mt * 16 + qr;
            int col = bn * 256 + wn * 32 + nt * 8 + tc;
            float b0 = bias[col], b1 = bias[col + 1];
            float2 o0 = make_float2(roundtf((acc[mt][nt][0] + b0) * scale),
                                    roundtf((acc[mt][nt][1] + b1) * scale));
            float2 o1 = make_float2(roundtf((acc[mt][nt][2] + b0) * scale),
                                    roundtf((acc[mt][nt][3] + b1) * scale));
            *(float2*)(C + (size_t)row * QKVDIM + col)       = o0;
            *(float2*)(C + (size_t)(row + 8) * QKVDIM + col) = o1;
        }
    }
}

// ---------------------------------------------------------------------------
// Attention via TF32 mma.sync: one block (256 thr) per bh; 2 CTAs/SM.
// SMEM (floats): Qs 128x68 @0, Ks 128x68 @8704, Vs 128x72 @17408.
// S (128x132) OVERLAYS Qs+Ks after the QK^T MMA (scores held in registers).
// All inputs pre-rounded tf32; P rounded at softmax store. Zero cvt in loops.
// ---------------------------------------------------------------------------
#define AT_K_F 8704
#define AT_V_F 17408
#define ATTN_SMEM_BYTES ((AT_V_F + 128 * 72) * 4)   // 106496

__global__ void __launch_bounds__(256, 2) attn_kernel(
    const float* __restrict__ qkv, float* __restrict__ attn,
    float* __restrict__ avg_out)
{
    extern __shared__ float sm[];
    float* Qs = sm;
    float* Ks = sm + AT_K_F;
    float* Vs = sm + AT_V_F;
    float* S  = sm;                 // overlays Qs+Ks after QK phase

    int bh  = blockIdx.x;
    int p   = bh >> 11;
    int rr  = bh & 2047;
    int nid = rr >> 4;
    int h   = rr & 15;
    int t   = threadIdx.x;
    int lane = t & 31;
    int wid  = t >> 5;            // 0..7
    int wm   = wid >> 2;          // 0..1
    int wn   = wid & 3;           // 0..3
    int col = h * HDIM;

    // ---- load Q, K, V tiles (tf32-rounded fp32, coalesced gather) ----
#pragma unroll
    for (int it = 0; it < 8; ++it) {
        int f  = t + it * 256;          // 0..2047
        int i  = f >> 4;                // row 0..127
        int d0 = (f & 15) << 2;         // 0..60
        int rowoff = ((2 * i + p) * 128 + nid) * QKVDIM;
        float4 q4 = *(const float4*)&qkv[rowoff + col + d0];
        float4 k4 = *(const float4*)&qkv[rowoff + 1024 + col + d0];
        float4 v4 = *(const float4*)&qkv[rowoff + 2048 + col + d0];
        *(float4*)&Qs[i * 68 + d0] = q4;
        *(float4*)&Ks[i * 68 + d0] = k4;
        *(float4*)&Vs[i * 72 + d0] = v4;
    }
    __syncthreads();

    int fr = lane >> 2;
    int fc = lane & 3;

    // ---- scores = Q K^T (TF32), warp tile 64x32, K=64; kept in registers ----
    float acc[4][4][4];
#pragma unroll
    for (int i = 0; i < 4; ++i)
#pragma unroll
        for (int j = 0; j < 4; ++j)
#pragma unroll
            for (int k = 0; k < 4; ++k) acc[i][j][k] = 0.f;

#pragma unroll
    for (int ks = 0; ks < 64; ks += 8) {
        uint32_t fa[4][4], fb[4][2];
#pragma unroll
        for (int mt = 0; mt < 4; ++mt) {
            int ar = wm * 64 + mt * 16 + fr;
            fa[mt][0] = __float_as_uint(Qs[ar * 68 + ks + fc]);
            fa[mt][1] = __float_as_uint(Qs[(ar + 8) * 68 + ks + fc]);
            fa[mt][2] = __float_as_uint(Qs[ar * 68 + ks + fc + 4]);
            fa[mt][3] = __float_as_uint(Qs[(ar + 8) * 68 + ks + fc + 4]);
        }
#pragma unroll
        for (int nt = 0; nt < 4; ++nt) {
            int nb = wn * 32 + nt * 8 + fr;
            fb[nt][0] = __float_as_uint(Ks[nb * 68 + ks + fc]);
            fb[nt][1] = __float_as_uint(Ks[nb * 68 + ks + fc + 4]);
        }
#pragma unroll
        for (int mt = 0; mt < 4; ++mt)
#pragma unroll
            for (int nt = 0; nt < 4; ++nt)
                mma_tf32(acc[mt][nt], fa[mt], fb[nt][0], fb[nt][1]);
    }
    __syncthreads();   // all warps done reading Qs/Ks before S overlays them

    {
        int qr = lane >> 2, tc = (lane & 3) * 2;
#pragma unroll
        for (int mt = 0; mt < 4; ++mt) {
#pragma unroll
            for (int nt = 0; nt < 4; ++nt) {
                int row = wm * 64 + mt * 16 + qr;
                int cc  = wn * 32 + nt * 8 + tc;
                S[row * 132 + cc]           = acc[mt][nt][0];
                S[row * 132 + cc + 1]       = acc[mt][nt][1];
                S[(row + 8) * 132 + cc]     = acc[mt][nt][2];
                S[(row + 8) * 132 + cc + 1] = acc[mt][nt][3];
            }
        }
    }
    __syncthreads();

    // ---- softmax: 16 rows per warp, lane-parallel; store tf32-rounded P ----
#pragma unroll
    for (int r8 = 0; r8 < 16; ++r8) {
        int row = wid * 16 + r8;
        float4 v = *(float4*)&S[row * 132 + lane * 4];
        float mx = fmaxf(fmaxf(v.x, v.y), fmaxf(v.z, v.w));
#pragma unroll
        for (int o = 16; o > 0; o >>= 1)
            mx = fmaxf(mx, __shfl_xor_sync(0xffffffffu, mx, o));
        v.x = __expf(v.x - mx); v.y = __expf(v.y - mx);
        v.z = __expf(v.z - mx); v.w = __expf(v.w - mx);
        float sum = v.x + v.y + v.z + v.w;
#pragma unroll
        for (int o = 16; o > 0; o >>= 1)
            sum += __shfl_xor_sync(0xffffffffu, sum, o);
        float inv = 1.0f / sum;
        v.x = roundtf(v.x * inv); v.y = roundtf(v.y * inv);
        v.z = roundtf(v.z * inv); v.w = roundtf(v.w * inv);
        *(float4*)&S[row * 132 + lane * 4] = v;
    }
    __syncthreads();

    // ---- avg_w: column sums over queries / H ----
    if (t < 128) {
        float s = 0.f;
        for (int i = 0; i < 128; ++i) s += S[i * 132 + t];
        avg_out[bh * 128 + t] = s * 0.0625f;
    }

    // ---- A·V (TF32): A = S directly, warp tile 64x16, K=128 ----
    {
        float av[4][2][4];
#pragma unroll
        for (int i = 0; i < 4; ++i)
#pragma unroll
            for (int j = 0; j < 2; ++j)
#pragma unroll
                for (int k = 0; k < 4; ++k) av[i][j][k] = 0.f;

#pragma unroll
        for (int ks = 0; ks < 128; ks += 8) {
            uint32_t fa[4][4], fb[2][2];
#pragma unroll
            for (int mt = 0; mt < 4; ++mt) {
                int ar = wm * 64 + mt * 16 + fr;
                fa[mt][0] = __float_as_uint(S[ar * 132 + ks + fc]);
                fa[mt][1] = __float_as_uint(S[(ar + 8) * 132 + ks + fc]);
                fa[mt][2] = __float_as_uint(S[ar * 132 + ks + fc + 4]);
                fa[mt][3] = __float_as_uint(S[(ar + 8) * 132 + ks + fc + 4]);
            }
#pragma unroll
            for (int nt = 0; nt < 2; ++nt) {
                int nb = wn * 16 + nt * 8 + fr;
                fb[nt][0] = __float_as_uint(Vs[(ks + fc) * 72 + nb]);
                fb[nt][1] = __float_as_uint(Vs[(ks + fc + 4) * 72 + nb]);
            }
#pragma unroll
            for (int mt = 0; mt < 4; ++mt)
#pragma unroll
                for (int nt = 0; nt < 2; ++nt)
                    mma_tf32(av[mt][nt], fa[mt], fb[nt][0], fb[nt][1]);
        }

        // epilogue: scatter through the inverse head-reshape
        int qr = lane >> 2, tc = (lane & 3) * 2;
#pragma unroll
        for (int mt = 0; mt < 4; ++mt) {
#pragma unroll
            for (int nt = 0; nt < 2; ++nt) {
                int row = wm * 64 + mt * 16 + qr;           // query index
                int cc  = wn * 16 + nt * 8 + tc;            // head-dim col
                int ob0 = ((2 * row + p) * 128 + nid) * EDIM + col + cc;
                int ob1 = ((2 * (row + 8) + p) * 128 + nid) * EDIM + col + cc;
                *(float2*)&attn[ob0] = make_float2(av[mt][nt][0], av[mt][nt][1]);
                *(float2*)&attn[ob1] = make_float2(av[mt][nt][2], av[mt][nt][3]);
            }
        }
    }
}

// ---------------------------------------------------------------------------
// Launch
// ---------------------------------------------------------------------------
extern "C" void kernel_launch(void* const* d_in, const int* in_sizes, int n_in,
                              void* d_out, int out_size)
{
    const float* x    = (const float*)d_in[0];
    const float* ln1w = (const float*)d_in[1];
    const float* ln1b = (const float*)d_in[2];
    const float* inw  = (const float*)d_in[3];
    const float* inb  = (const float*)d_in[4];
    const float* ln2w = (const float*)d_in[5];
    const float* ln2b = (const float*)d_in[6];
    float* out = (float*)d_out;

    float *xn, *qkv, *attn, *wtf;
    cudaGetSymbolAddress((void**)&xn,   g_xn);
    cudaGetSymbolAddress((void**)&qkv,  g_qkv);
    cudaGetSymbolAddress((void**)&attn, g_attn);
    cudaGetSymbolAddress((void**)&wtf,  g_wtf);

    cudaFuncSetAttribute(attn_kernel,
                         cudaFuncAttributeMaxDynamicSharedMemorySize,
                         ATTN_SMEM_BYTES);
    cudaFuncSetAttribute(qkv_gemm_tf32_kernel,
                         cudaFuncAttributeMaxDynamicSharedMemorySize,
                         GS_SMEM);
    cudaFuncSetAttribute(permute_w_kernel,
                         cudaFuncAttributeMaxDynamicSharedMemorySize,
                         PW_SMEM);

    // 1) xn = LN1(x), tf32-rounded (also the residual for LN2)
    ln_kernel<<<NROWS, 256>>>(x, nullptr, ln1w, ln1b, xn, 1);
    // 2) permute + round weights into B-fragment layout
    permute_w_kernel<<<192, 256, PW_SMEM>>>(inw, wtf);
    // 3) TF32 QKV GEMM (bias + q-scale fused, rounded output)
    qkv_gemm_tf32_kernel<<<dim3(12, 256), 512, GS_SMEM>>>(xn, wtf, inb, qkv);
    // 4) TF32 attention + avg_w (2 CTAs/SM)
    attn_kernel<<<NBH, 256, ATTN_SMEM_BYTES>>>(qkv, attn, out + OUT_ELEMS);
    // 5) out = LN2(xn + attn)
    ln_kernel<<<NROWS, 256>>>(xn, attn, ln2w, ln2b, out, 0);
}

// round 10
// speedup vs baseline: 3.4338x; 1.0356x over previous
#include <cuda_runtime.h>
#include <cstdint>

// ---------------------------------------------------------------------------
// Problem constants
// ---------------------------------------------------------------------------
#define EDIM   1024
#define NAQ    128
#define BSZ    256
#define NROWS  (BSZ * NAQ)          // 32768
#define QKVDIM 3072
#define HEADS  16
#define HDIM   64
#define NBH    (BSZ * HEADS)        // 4096 attention batches
#define OUT_ELEMS (NROWS * EDIM)

// ---------------------------------------------------------------------------
// Scratch (device globals: allocation-free)
// ---------------------------------------------------------------------------
__device__ float g_xn  [(size_t)NROWS * EDIM];       // ln1(x), tf32-rounded
__device__ float g_qkv [(size_t)NROWS * QKVDIM];     // qkv (q scaled), tf32-rounded
__device__ float g_attn[(size_t)NROWS * EDIM];       // attention output
__device__ float g_wtf [(size_t)QKVDIM * EDIM];      // in_w, fragment-permuted tf32

// ---------------------------------------------------------------------------
// Helpers (portable subset: harness lowers through compute_103)
// ---------------------------------------------------------------------------
__device__ __forceinline__ uint32_t smem_u32(const void* p) {
    uint32_t a;
    asm("{ .reg .u64 t; cvta.to.shared.u64 t, %1; cvt.u32.u64 %0, t; }"
        : "=r"(a) : "l"(p));
    return a;
}
__device__ __forceinline__ void cp_async16(uint32_t dst, const void* src) {
    asm volatile("cp.async.cg.shared.global [%0], [%1], 16;"
                 :: "r"(dst), "l"(src) : "memory");
}
#define CP_COMMIT() asm volatile("cp.async.commit_group;" ::: "memory")

__device__ __forceinline__ uint32_t f2tf(float f) {
    uint32_t r;
    asm("cvt.rna.tf32.f32 %0, %1;" : "=r"(r) : "f"(f));
    return r;
}
__device__ __forceinline__ float roundtf(float f) {
    return __uint_as_float(f2tf(f));
}
__device__ __forceinline__ void mma_tf32(float* c, const uint32_t* a,
                                         uint32_t b0, uint32_t b1) {
    asm volatile(
        "mma.sync.aligned.m16n8k8.row.col.f32.tf32.tf32.f32 "
        "{%0,%1,%2,%3}, {%4,%5,%6,%7}, {%8,%9}, {%0,%1,%2,%3};"
        : "+f"(c[0]), "+f"(c[1]), "+f"(c[2]), "+f"(c[3])
        : "r"(a[0]), "r"(a[1]), "r"(a[2]), "r"(a[3]), "r"(b0), "r"(b1));
}
// ldmatrix x4 (b16 view): loads 4 8-row x 16B blocks; per-lane row address.
__device__ __forceinline__ void ldsm4(uint32_t* r, uint32_t addr) {
    asm volatile("ldmatrix.sync.aligned.m8n8.x4.shared.b16 {%0,%1,%2,%3}, [%4];"
                 : "=r"(r[0]), "=r"(r[1]), "=r"(r[2]), "=r"(r[3]) : "r"(addr));
}

// ---------------------------------------------------------------------------
// LayerNorm (+ optional residual, optional tf32 rounding of output)
// ---------------------------------------------------------------------------
__global__ __launch_bounds__(256) void ln_kernel(
    const float* __restrict__ in, const float* __restrict__ res,
    const float* __restrict__ w, const float* __restrict__ b,
    float* __restrict__ out, int rnd)
{
    __shared__ float red_s[8];
    __shared__ float red_q[8];
    size_t row = blockIdx.x;
    int t = threadIdx.x;

    const float4* px = (const float4*)(in + row * EDIM);
    float4 v = px[t];
    if (res != nullptr) {
        const float4* pr = (const float4*)(res + row * EDIM);
        float4 rv = pr[t];
        v.x += rv.x; v.y += rv.y; v.z += rv.z; v.w += rv.w;
    }
    float s = v.x + v.y + v.z + v.w;
    float q = v.x * v.x + v.y * v.y + v.z * v.z + v.w * v.w;
#pragma unroll
    for (int o = 16; o > 0; o >>= 1) {
        s += __shfl_xor_sync(0xffffffffu, s, o);
        q += __shfl_xor_sync(0xffffffffu, q, o);
    }
    if ((t & 31) == 0) { red_s[t >> 5] = s; red_q[t >> 5] = q; }
    __syncthreads();
    float tot = 0.f, totq = 0.f;
#pragma unroll
    for (int k = 0; k < 8; ++k) { tot += red_s[k]; totq += red_q[k]; }

    float mean = tot * (1.0f / EDIM);
    float var  = totq * (1.0f / EDIM) - mean * mean;
    float rstd = rsqrtf(var + 1e-5f);

    int c0 = t * 4;
    float4 wv = *(const float4*)(w + c0);
    float4 bv = *(const float4*)(b + c0);
    float4 o4;
    o4.x = (v.x - mean) * rstd * wv.x + bv.x;
    o4.y = (v.y - mean) * rstd * wv.y + bv.y;
    o4.z = (v.z - mean) * rstd * wv.z + bv.z;
    o4.w = (v.w - mean) * rstd * wv.w + bv.w;
    if (rnd) {
        o4.x = roundtf(o4.x); o4.y = roundtf(o4.y);
        o4.z = roundtf(o4.z); o4.w = roundtf(o4.w);
    }
    ((float4*)(out + row * EDIM))[t] = o4;
}

// ---------------------------------------------------------------------------
// Weight permute: in_w (3072x1024 row-major fp32) -> B-fragment order, tf32.
// Output: [nb 0..383][kb 0..127][lane 0..31][2]
//   val = { W[8nb+fr][8kb+fc], W[8nb+fr][8kb+fc+4] },  fr=lane>>2, fc=lane&3
// ---------------------------------------------------------------------------
#define PW_SMEM (16 * 1028 * 4)     // 65792 bytes

__global__ __launch_bounds__(256) void permute_w_kernel(
    const float* __restrict__ w, float* __restrict__ wp)
{
    extern __shared__ float s[];
    int blk = blockIdx.x;           // 0..191
    int t = threadIdx.x;
#pragma unroll
    for (int rr = 0; rr < 16; ++rr) {
        float4 v = *(const float4*)(w + (size_t)(blk * 16 + rr) * EDIM + t * 4);
        *(float4*)&s[rr * 1028 + t * 4] = v;
    }
    __syncthreads();
#pragma unroll
    for (int it = 0; it < 32; ++it) {
        int o2 = t + it * 256;              // 0..8191
        int nb_l = o2 >> 12;                // 0..1
        int kb   = (o2 >> 5) & 127;
        int lane = o2 & 31;
        int fr = lane >> 2, fc = lane & 3;
        int rl = nb_l * 8 + fr;
        float2 o;
        o.x = roundtf(s[rl * 1028 + kb * 8 + fc]);
        o.y = roundtf(s[rl * 1028 + kb * 8 + fc + 4]);
        *(float2*)(wp + (((size_t)(blk * 2 + nb_l) * 128 + kb) * 32 + lane) * 2) = o;
    }
}

// ---------------------------------------------------------------------------
// QKV GEMM via TF32 mma.sync (pre-rounded inputs, LDSM A-fragments):
//   C[m,n] = (sum_k A[m,k]*W[n,k] + bias[n]) * (n < 1024 ? 0.125 : 1), rounded
// CTA tile 128(M) x 256(N), BK=32, 256 threads (8 warps 2x4),
// warp tile 64x64 (128B smem per MMA), 4-stage cp.async pipeline.
// ---------------------------------------------------------------------------
#define GS_A_BYTES 18432
#define GS_B_BYTES 32768
#define GS_STAGE   (GS_A_BYTES + GS_B_BYTES)   // 51200
#define GS_SMEM    (4 * GS_STAGE)              // 204800

__global__ __launch_bounds__(256, 1) void qkv_gemm_tf32_kernel(
    const float* __restrict__ A, const float* __restrict__ Wp,
    const float* __restrict__ bias, float* __restrict__ C)
{
    extern __shared__ char smem[];
    uint32_t sb = smem_u32(smem);
    int tid  = threadIdx.x;
    int lane = tid & 31;
    int wid  = tid >> 5;          // 0..7
    int wm   = wid >> 2;          // 0..1
    int wn   = wid & 3;           // 0..3
    int bn = blockIdx.x;          // 0..11
    int bm = blockIdx.y;          // 0..255

    auto load_stage = [&](int c, int s) {
        uint32_t base = sb + s * GS_STAGE;
        int kbase = c * 32;
#pragma unroll
        for (int i = 0; i < 4; ++i) {      // A: 1024 granules
            int g = tid + i * 256;
            int r = g >> 3, kk = g & 7;
            cp_async16(base + r * 144 + kk * 16,
                       A + (size_t)(bm * 128 + r) * EDIM + kbase + kk * 4);
        }
#pragma unroll
        for (int i = 0; i < 8; ++i) {      // W: 2048 granules (permuted blocks)
            int g = tid + i * 256;
            int nb = g >> 6, kb = (g >> 4) & 3, pr = g & 15;
            cp_async16(base + GS_A_BYTES + g * 16,
                       Wp + ((size_t)(bn * 32 + nb) * 128 + c * 4 + kb) * 64 + pr * 4);
        }
    };

    load_stage(0, 0); CP_COMMIT();
    load_stage(1, 1); CP_COMMIT();
    load_stage(2, 2); CP_COMMIT();

    float acc[4][8][4];
#pragma unroll
    for (int i = 0; i < 4; ++i)
#pragma unroll
        for (int j = 0; j < 8; ++j)
#pragma unroll
            for (int k = 0; k < 4; ++k) acc[i][j][k] = 0.f;

    // LDSM per-lane byte offset within A tile:
    //   row = wm*64 + mt*16 + (lane&15), col = ks + (lane>>4)*4
    uint32_t a_off = (uint32_t)((wm * 64 + (lane & 15)) * 144 + (lane >> 4) * 16);

    for (int c = 0; c < 32; ++c) {
        asm volatile("cp.async.wait_group 2;" ::: "memory");
        __syncthreads();
        int s = c & 3;
        uint32_t sA = sb + s * GS_STAGE;
        const char* Bp = smem + s * GS_STAGE + GS_A_BYTES;

#pragma unroll
        for (int ks = 0; ks < 32; ks += 8) {
            int kb = ks >> 3;
            uint32_t fa[4][4];
            uint2 fb[8];
#pragma unroll
            for (int mt = 0; mt < 4; ++mt)
                ldsm4(fa[mt], sA + a_off + mt * (16 * 144) + ks * 4);
#pragma unroll
            for (int nt = 0; nt < 8; ++nt) {
                int nbl = wn * 8 + nt;
                fb[nt] = *(const uint2*)(Bp + (nbl * 4 + kb) * 256 + lane * 8);
            }
#pragma unroll
            for (int mt = 0; mt < 4; ++mt)
#pragma unroll
                for (int nt = 0; nt < 8; ++nt)
                    mma_tf32(acc[mt][nt], fa[mt], fb[nt].x, fb[nt].y);
        }

        if (c + 3 < 32) load_stage(c + 3, (c + 3) & 3);
        CP_COMMIT();
    }

    // epilogue: bias + q-scale fused, tf32-rounded stores
    int qr = lane >> 2;
    int tc = (lane & 3) * 2;
    float scale = (bn < 4) ? 0.125f : 1.0f;   // q * HD^-0.5
#pragma unroll
    for (int mt = 0; mt < 4; ++mt) {
#pragma unroll
        for (int nt = 0; nt < 8; ++nt) {
            int row = bm * 128 + wm * 64 + mt * 16 + qr;
            int col = bn * 256 + wn * 64 + nt * 8 + tc;
            float b0 = bias[col], b1 = bias[col + 1];
            float2 o0 = make_float2(roundtf((acc[mt][nt][0] + b0) * scale),
                                    roundtf((acc[mt][nt][1] + b1) * scale));
            float2 o1 = make_float2(roundtf((acc[mt][nt][2] + b0) * scale),
                                    roundtf((acc[mt][nt][3] + b1) * scale));
            *(float2*)(C + (size_t)row * QKVDIM + col)       = o0;
            *(float2*)(C + (size_t)(row + 8) * QKVDIM + col) = o1;
        }
    }
}

// ---------------------------------------------------------------------------
// Attention via TF32 mma.sync + LDSM: one block (256 thr) per bh; 2 CTAs/SM.
// SMEM (floats): Qs 128x68 @0, Ks 128x68 @8704, Vs 128x72 @17408,
//   AVG partials 256 @26624.  S (128x132) overlays Qs+Ks after QK^T.
// ---------------------------------------------------------------------------
#define AT_K_F   8704
#define AT_V_F   17408
#define AT_AVG_F 26624
#define ATTN_SMEM_BYTES ((AT_AVG_F + 256) * 4)   // 107520

__global__ void __launch_bounds__(256, 2) attn_kernel(
    const float* __restrict__ qkv, float* __restrict__ attn,
    float* __restrict__ avg_out)
{
    extern __shared__ float sm[];
    float* Qs  = sm;
    float* Ks  = sm + AT_K_F;
    float* Vs  = sm + AT_V_F;
    float* AVG = sm + AT_AVG_F;
    float* S   = sm;                // overlays Qs+Ks after QK phase
    uint32_t sbase = smem_u32(sm);

    int bh  = blockIdx.x;
    int p   = bh >> 11;
    int rr  = bh & 2047;
    int nid = rr >> 4;
    int h   = rr & 15;
    int t   = threadIdx.x;
    int lane = t & 31;
    int wid  = t >> 5;            // 0..7
    int wm   = wid >> 2;          // 0..1
    int wn   = wid & 3;           // 0..3
    int col = h * HDIM;

    // ---- load Q, K, V tiles (tf32-rounded fp32, coalesced gather) ----
#pragma unroll
    for (int it = 0; it < 8; ++it) {
        int f  = t + it * 256;          // 0..2047
        int i  = f >> 4;                // row 0..127
        int d0 = (f & 15) << 2;         // 0..60
        int rowoff = ((2 * i + p) * 128 + nid) * QKVDIM;
        float4 q4 = *(const float4*)&qkv[rowoff + col + d0];
        float4 k4 = *(const float4*)&qkv[rowoff + 1024 + col + d0];
        float4 v4 = *(const float4*)&qkv[rowoff + 2048 + col + d0];
        *(float4*)&Qs[i * 68 + d0] = q4;
        *(float4*)&Ks[i * 68 + d0] = k4;
        *(float4*)&Vs[i * 72 + d0] = v4;
    }
    __syncthreads();

    int fr = lane >> 2;
    int fc = lane & 3;

    // LDSM per-lane offsets (bytes):
    // A-fragment: row = base + mt*16 + (lane&15), col = ks + (lane>>4)*4
    uint32_t aq_off = (uint32_t)((wm * 64 + (lane & 15)) * 272 + (lane >> 4) * 16);
    // K B-fragment pair: row = wn*32 + ntp*16 + (lane&7) + ((lane&16)>>1),
    //                    col = ks + ((lane>>3)&1)*4
    uint32_t bk_row = (uint32_t)(wn * 32 + (lane & 7) + ((lane & 16) >> 1));
    uint32_t bk_off = AT_K_F * 4 + bk_row * 272 + (((lane >> 3) & 1) * 16);

    // ---- scores = Q K^T (TF32), warp tile 64x32, K=64; kept in registers ----
    float acc[4][4][4];
#pragma unroll
    for (int i = 0; i < 4; ++i)
#pragma unroll
        for (int j = 0; j < 4; ++j)
#pragma unroll
            for (int k = 0; k < 4; ++k) acc[i][j][k] = 0.f;

#pragma unroll
    for (int ks = 0; ks < 64; ks += 8) {
        uint32_t fa[4][4], fbp[2][4];
#pragma unroll
        for (int mt = 0; mt < 4; ++mt)
            ldsm4(fa[mt], sbase + aq_off + mt * (16 * 272) + ks * 4);
#pragma unroll
        for (int ntp = 0; ntp < 2; ++ntp)
            ldsm4(fbp[ntp], sbase + bk_off + ntp * (16 * 272) + ks * 4);
#pragma unroll
        for (int mt = 0; mt < 4; ++mt) {
#pragma unroll
            for (int nt = 0; nt < 4; ++nt) {
                int np = nt >> 1, hh = (nt & 1) * 2;
                mma_tf32(acc[mt][nt], fa[mt], fbp[np][hh], fbp[np][hh + 1]);
            }
        }
    }
    __syncthreads();   // all warps done reading Qs/Ks before S overlays them

    {
        int qr = lane >> 2, tc = (lane & 3) * 2;
#pragma unroll
        for (int mt = 0; mt < 4; ++mt) {
#pragma unroll
            for (int nt = 0; nt < 4; ++nt) {
                int row = wm * 64 + mt * 16 + qr;
                int cc  = wn * 32 + nt * 8 + tc;
                S[row * 132 + cc]           = acc[mt][nt][0];
                S[row * 132 + cc + 1]       = acc[mt][nt][1];
                S[(row + 8) * 132 + cc]     = acc[mt][nt][2];
                S[(row + 8) * 132 + cc + 1] = acc[mt][nt][3];
            }
        }
    }
    __syncthreads();

    // ---- softmax: 16 rows per warp, lane-parallel; store tf32-rounded P ----
#pragma unroll
    for (int r8 = 0; r8 < 16; ++r8) {
        int row = wid * 16 + r8;
        float4 v = *(float4*)&S[row * 132 + lane * 4];
        float mx = fmaxf(fmaxf(v.x, v.y), fmaxf(v.z, v.w));
#pragma unroll
        for (int o = 16; o > 0; o >>= 1)
            mx = fmaxf(mx, __shfl_xor_sync(0xffffffffu, mx, o));
        v.x = __expf(v.x - mx); v.y = __expf(v.y - mx);
        v.z = __expf(v.z - mx); v.w = __expf(v.w - mx);
        float sum = v.x + v.y + v.z + v.w;
#pragma unroll
        for (int o = 16; o > 0; o >>= 1)
            sum += __shfl_xor_sync(0xffffffffu, sum, o);
        float inv = 1.0f / sum;
        v.x = roundtf(v.x * inv); v.y = roundtf(v.y * inv);
        v.z = roundtf(v.z * inv); v.w = roundtf(v.w * inv);
        *(float4*)&S[row * 132 + lane * 4] = v;
    }
    __syncthreads();

    // ---- avg_w: column sums over queries / H, split across 256 threads ----
    {
        int colx = t & 127;
        int half = t >> 7;          // 0 or 1
        int i0 = half * 64;
        float s0 = 0.f, s1 = 0.f;
#pragma unroll 8
        for (int i = 0; i < 64; i += 2) {
            s0 += S[(i0 + i) * 132 + colx];
            s1 += S[(i0 + i + 1) * 132 + colx];
        }
        AVG[t] = s0 + s1;
    }
    __syncthreads();
    if (t < 128)
        avg_out[bh * 128 + t] = (AVG[t] + AVG[t + 128]) * 0.0625f;

    // ---- A·V (TF32): A = S via LDSM, warp tile 64x16, K=128 ----
    {
        uint32_t as_off = (uint32_t)((wm * 64 + (lane & 15)) * 528 + (lane >> 4) * 16);
        float av[4][2][4];
#pragma unroll
        for (int i = 0; i < 4; ++i)
#pragma unroll
            for (int j = 0; j < 2; ++j)
#pragma unroll
                for (int k = 0; k < 4; ++k) av[i][j][k] = 0.f;

#pragma unroll
        for (int ks = 0; ks < 128; ks += 8) {
            uint32_t fa[4][4], fb[2][2];
#pragma unroll
            for (int mt = 0; mt < 4; ++mt)
                ldsm4(fa[mt], sbase + as_off + mt * (16 * 528) + ks * 4);
#pragma unroll
            for (int nt = 0; nt < 2; ++nt) {
                int nb = wn * 16 + nt * 8 + fr;
                fb[nt][0] = __float_as_uint(Vs[(ks + fc) * 72 + nb]);
                fb[nt][1] = __float_as_uint(Vs[(ks + fc + 4) * 72 + nb]);
            }
#pragma unroll
            for (int mt = 0; mt < 4; ++mt)
#pragma unroll
                for (int nt = 0; nt < 2; ++nt)
                    mma_tf32(av[mt][nt], fa[mt], fb[nt][0], fb[nt][1]);
        }

        // epilogue: scatter through the inverse head-reshape
        int qr = lane >> 2, tc = (lane & 3) * 2;
#pragma unroll
        for (int mt = 0; mt < 4; ++mt) {
#pragma unroll
            for (int nt = 0; nt < 2; ++nt) {
                int row = wm * 64 + mt * 16 + qr;           // query index
                int cc  = wn * 16 + nt * 8 + tc;            // head-dim col
                int ob0 = ((2 * row + p) * 128 + nid) * EDIM + col + cc;
                int ob1 = ((2 * (row + 8) + p) * 128 + nid) * EDIM + col + cc;
                *(float2*)&attn[ob0] = make_float2(av[mt][nt][0], av[mt][nt][1]);
                *(float2*)&attn[ob1] = make_float2(av[mt][nt][2], av[mt][nt][3]);
            }
        }
    }
}

// ---------------------------------------------------------------------------
// Launch
// ---------------------------------------------------------------------------
extern "C" void kernel_launch(void* const* d_in, const int* in_sizes, int n_in,
                              void* d_out, int out_size)
{
    const float* x    = (const float*)d_in[0];
    const float* ln1w = (const float*)d_in[1];
    const float* ln1b = (const float*)d_in[2];
    const float* inw  = (const float*)d_in[3];
    const float* inb  = (const float*)d_in[4];
    const float* ln2w = (const float*)d_in[5];
    const float* ln2b = (const float*)d_in[6];
    float* out = (float*)d_out;

    float *xn, *qkv, *attn, *wtf;
    cudaGetSymbolAddress((void**)&xn,   g_xn);
    cudaGetSymbolAddress((void**)&qkv,  g_qkv);
    cudaGetSymbolAddress((void**)&attn, g_attn);
    cudaGetSymbolAddress((void**)&wtf,  g_wtf);

    cudaFuncSetAttribute(attn_kernel,
                         cudaFuncAttributeMaxDynamicSharedMemorySize,
                         ATTN_SMEM_BYTES);
    cudaFuncSetAttribute(qkv_gemm_tf32_kernel,
                         cudaFuncAttributeMaxDynamicSharedMemorySize,
                         GS_SMEM);
    cudaFuncSetAttribute(permute_w_kernel,
                         cudaFuncAttributeMaxDynamicSharedMemorySize,
                         PW_SMEM);

    // 1) xn = LN1(x), tf32-rounded (also the residual for LN2)
    ln_kernel<<<NROWS, 256>>>(x, nullptr, ln1w, ln1b, xn, 1);
    // 2) permute + round weights into B-fragment layout
    permute_w_kernel<<<192, 256, PW_SMEM>>>(inw, wtf);
    // 3) TF32 QKV GEMM (64x64 warp tiles, LDSM A-fragments)
    qkv_gemm_tf32_kernel<<<dim3(12, 256), 256, GS_SMEM>>>(xn, wtf, inb, qkv);
    // 4) TF32 attention + avg_w (2 CTAs/SM, LDSM fragments)
    attn_kernel<<<NBH, 256, ATTN_SMEM_BYTES>>>(qkv, attn, out + OUT_ELEMS);
    // 5) out = LN2(xn + attn)
    ln_kernel<<<NROWS, 256>>>(xn, attn, ln2w, ln2b, out, 0);
}

// round 11
// speedup vs baseline: 3.4541x; 1.0059x over previous
#include <cuda_runtime.h>
#include <cstdint>

// ---------------------------------------------------------------------------
// Problem constants
// ---------------------------------------------------------------------------
#define EDIM   1024
#define NAQ    128
#define BSZ    256
#define NROWS  (BSZ * NAQ)          // 32768
#define QKVDIM 3072
#define HEADS  16
#define HDIM   64
#define NBH    (BSZ * HEADS)        // 4096 attention batches
#define OUT_ELEMS (NROWS * EDIM)
#define NTILES 3072                 // 12 bn x 256 bm
#define NSM    148

// ---------------------------------------------------------------------------
// Scratch (device globals: allocation-free)
// ---------------------------------------------------------------------------
__device__ float g_xn  [(size_t)NROWS * EDIM];       // ln1(x), tf32-rounded
__device__ float g_qkv [(size_t)NROWS * QKVDIM];     // qkv (q scaled), tf32-rounded
__device__ float g_attn[(size_t)NROWS * EDIM];       // attention output
__device__ float g_wtf [(size_t)QKVDIM * EDIM];      // in_w, fragment-permuted tf32

// ---------------------------------------------------------------------------
// Helpers (portable subset: harness lowers through compute_103)
// ---------------------------------------------------------------------------
__device__ __forceinline__ uint32_t smem_u32(const void* p) {
    uint32_t a;
    asm("{ .reg .u64 t; cvta.to.shared.u64 t, %1; cvt.u32.u64 %0, t; }"
        : "=r"(a) : "l"(p));
    return a;
}
__device__ __forceinline__ void cp_async16(uint32_t dst, const void* src) {
    asm volatile("cp.async.cg.shared.global [%0], [%1], 16;"
                 :: "r"(dst), "l"(src) : "memory");
}
#define CP_COMMIT() asm volatile("cp.async.commit_group;" ::: "memory")

__device__ __forceinline__ uint32_t f2tf(float f) {
    uint32_t r;
    asm("cvt.rna.tf32.f32 %0, %1;" : "=r"(r) : "f"(f));
    return r;
}
__device__ __forceinline__ float roundtf(float f) {
    return __uint_as_float(f2tf(f));
}
__device__ __forceinline__ void mma_tf32(float* c, const uint32_t* a,
                                         uint32_t b0, uint32_t b1) {
    asm volatile(
        "mma.sync.aligned.m16n8k8.row.col.f32.tf32.tf32.f32 "
        "{%0,%1,%2,%3}, {%4,%5,%6,%7}, {%8,%9}, {%0,%1,%2,%3};"
        : "+f"(c[0]), "+f"(c[1]), "+f"(c[2]), "+f"(c[3])
        : "r"(a[0]), "r"(a[1]), "r"(a[2]), "r"(a[3]), "r"(b0), "r"(b1));
}
__device__ __forceinline__ void ldsm4(uint32_t* r, uint32_t addr) {
    asm volatile("ldmatrix.sync.aligned.m8n8.x4.shared.b16 {%0,%1,%2,%3}, [%4];"
                 : "=r"(r[0]), "=r"(r[1]), "=r"(r[2]), "=r"(r[3]) : "r"(addr));
}

// ---------------------------------------------------------------------------
// LayerNorm (+ optional residual, optional tf32 rounding of output)
// ---------------------------------------------------------------------------
__global__ __launch_bounds__(256) void ln_kernel(
    const float* __restrict__ in, const float* __restrict__ res,
    const float* __restrict__ w, const float* __restrict__ b,
    float* __restrict__ out, int rnd)
{
    __shared__ float red_s[8];
    __shared__ float red_q[8];
    size_t row = blockIdx.x;
    int t = threadIdx.x;

    const float4* px = (const float4*)(in + row * EDIM);
    float4 v = px[t];
    if (res != nullptr) {
        const float4* pr = (const float4*)(res + row * EDIM);
        float4 rv = pr[t];
        v.x += rv.x; v.y += rv.y; v.z += rv.z; v.w += rv.w;
    }
    float s = v.x + v.y + v.z + v.w;
    float q = v.x * v.x + v.y * v.y + v.z * v.z + v.w * v.w;
#pragma unroll
    for (int o = 16; o > 0; o >>= 1) {
        s += __shfl_xor_sync(0xffffffffu, s, o);
        q += __shfl_xor_sync(0xffffffffu, q, o);
    }
    if ((t & 31) == 0) { red_s[t >> 5] = s; red_q[t >> 5] = q; }
    __syncthreads();
    float tot = 0.f, totq = 0.f;
#pragma unroll
    for (int k = 0; k < 8; ++k) { tot += red_s[k]; totq += red_q[k]; }

    float mean = tot * (1.0f / EDIM);
    float var  = totq * (1.0f / EDIM) - mean * mean;
    float rstd = rsqrtf(var + 1e-5f);

    int c0 = t * 4;
    float4 wv = *(const float4*)(w + c0);
    float4 bv = *(const float4*)(b + c0);
    float4 o4;
    o4.x = (v.x - mean) * rstd * wv.x + bv.x;
    o4.y = (v.y - mean) * rstd * wv.y + bv.y;
    o4.z = (v.z - mean) * rstd * wv.z + bv.z;
    o4.w = (v.w - mean) * rstd * wv.w + bv.w;
    if (rnd) {
        o4.x = roundtf(o4.x); o4.y = roundtf(o4.y);
        o4.z = roundtf(o4.z); o4.w = roundtf(o4.w);
    }
    ((float4*)(out + row * EDIM))[t] = o4;
}

// ---------------------------------------------------------------------------
// Weight permute: in_w (3072x1024 row-major fp32) -> B-fragment order, tf32.
// Output: [nb 0..383][kb 0..127][lane 0..31][2]
//   val = { W[8nb+fr][8kb+fc], W[8nb+fr][8kb+fc+4] },  fr=lane>>2, fc=lane&3
// ---------------------------------------------------------------------------
#define PW_SMEM (16 * 1028 * 4)     // 65792 bytes

__global__ __launch_bounds__(256) void permute_w_kernel(
    const float* __restrict__ w, float* __restrict__ wp)
{
    extern __shared__ float s[];
    int blk = blockIdx.x;           // 0..191
    int t = threadIdx.x;
#pragma unroll
    for (int rr = 0; rr < 16; ++rr) {
        float4 v = *(const float4*)(w + (size_t)(blk * 16 + rr) * EDIM + t * 4);
        *(float4*)&s[rr * 1028 + t * 4] = v;
    }
    __syncthreads();
#pragma unroll
    for (int it = 0; it < 32; ++it) {
        int o2 = t + it * 256;              // 0..8191
        int nb_l = o2 >> 12;                // 0..1
        int kb   = (o2 >> 5) & 127;
        int lane = o2 & 31;
        int fr = lane >> 2, fc = lane & 3;
        int rl = nb_l * 8 + fr;
        float2 o;
        o.x = roundtf(s[rl * 1028 + kb * 8 + fc]);
        o.y = roundtf(s[rl * 1028 + kb * 8 + fc + 4]);
        *(float2*)(wp + (((size_t)(blk * 2 + nb_l) * 128 + kb) * 32 + lane) * 2) = o;
    }
}

// ---------------------------------------------------------------------------
// Persistent TF32 QKV GEMM. 148 CTAs, each owns ~21 tiles of 128(M)x256(N).
// 4-stage cp.async pipeline runs CONTINUOUSLY across tile boundaries:
// chunk q = (local_tile << 5) | c, slot = q & 3. Epilogues overlap loads.
// 8 warps (2x4), warp tile 64x64, LDSM A-fragments, permuted-W LDS.64 B.
// ---------------------------------------------------------------------------
#define GS_A_BYTES 18432
#define GS_B_BYTES 32768
#define GS_STAGE   (GS_A_BYTES + GS_B_BYTES)   // 51200
#define GS_SMEM    (4 * GS_STAGE)              // 204800

__global__ __launch_bounds__(256, 1) void qkv_gemm_tf32_kernel(
    const float* __restrict__ A, const float* __restrict__ Wp,
    const float* __restrict__ bias, float* __restrict__ C)
{
    extern __shared__ char smem[];
    uint32_t sb = smem_u32(smem);
    int tid  = threadIdx.x;
    int lane = tid & 31;
    int wid  = tid >> 5;          // 0..7
    int wm   = wid >> 2;          // 0..1
    int wn   = wid & 3;           // 0..3
    int bid  = blockIdx.x;        // 0..147

    int nt_local = (NTILES - bid + NSM - 1) / NSM;
    int total_chunks = nt_local * 32;

    auto load_chunk = [&](int q) {
        int tile = bid + (q >> 5) * NSM;
        int c    = q & 31;
        int bn = tile >> 8;                 // 0..11
        int bm = tile & 255;                // 0..255
        uint32_t base = sb + (q & 3) * GS_STAGE;
        int kbase = c * 32;
#pragma unroll
        for (int i = 0; i < 4; ++i) {      // A: 1024 granules
            int g = tid + i * 256;
            int r = g >> 3, kk = g & 7;
            cp_async16(base + r * 144 + kk * 16,
                       A + (size_t)(bm * 128 + r) * EDIM + kbase + kk * 4);
        }
#pragma unroll
        for (int i = 0; i < 8; ++i) {      // W: 2048 granules (permuted blocks)
            int g = tid + i * 256;
            int nb = g >> 6, kb = (g >> 4) & 3, pr = g & 15;
            cp_async16(base + GS_A_BYTES + g * 16,
                       Wp + ((size_t)(bn * 32 + nb) * 128 + c * 4 + kb) * 64 + pr * 4);
        }
    };

    load_chunk(0); CP_COMMIT();
    load_chunk(1); CP_COMMIT();
    load_chunk(2); CP_COMMIT();

    float acc[4][8][4];
#pragma unroll
    for (int i = 0; i < 4; ++i)
#pragma unroll
        for (int j = 0; j < 8; ++j)
#pragma unroll
            for (int k = 0; k < 4; ++k) acc[i][j][k] = 0.f;

    uint32_t a_off = (uint32_t)((wm * 64 + (lane & 15)) * 144 + (lane >> 4) * 16);
    int qr = lane >> 2;
    int tc = (lane & 3) * 2;

    for (int q = 0; q < total_chunks; ++q) {
        asm volatile("cp.async.wait_group 2;" ::: "memory");
        __syncthreads();
        int s = q & 3;
        uint32_t sA = sb + s * GS_STAGE;
        const char* Bp = smem + s * GS_STAGE + GS_A_BYTES;

#pragma unroll
        for (int ks = 0; ks < 32; ks += 8) {
            int kb = ks >> 3;
            uint32_t fa[4][4];
            uint2 fb[8];
#pragma unroll
            for (int mt = 0; mt < 4; ++mt)
                ldsm4(fa[mt], sA + a_off + mt * (16 * 144) + ks * 4);
#pragma unroll
            for (int nt = 0; nt < 8; ++nt) {
                int nbl = wn * 8 + nt;
                fb[nt] = *(const uint2*)(Bp + (nbl * 4 + kb) * 256 + lane * 8);
            }
#pragma unroll
            for (int mt = 0; mt < 4; ++mt)
#pragma unroll
                for (int nt = 0; nt < 8; ++nt)
                    mma_tf32(acc[mt][nt], fa[mt], fb[nt].x, fb[nt].y);
        }

        if (q + 3 < total_chunks) load_chunk(q + 3);
        CP_COMMIT();

        if ((q & 31) == 31) {
            // ---- epilogue for this tile (loads for next tile in flight) ----
            int tile = bid + (q >> 5) * NSM;
            int bn = tile >> 8;
            int bm = tile & 255;
            float scale = (bn < 4) ? 0.125f : 1.0f;   // q * HD^-0.5
#pragma unroll
            for (int mt = 0; mt < 4; ++mt) {
#pragma unroll
                for (int nt = 0; nt < 8; ++nt) {
                    int row = bm * 128 + wm * 64 + mt * 16 + qr;
                    int col = bn * 256 + wn * 64 + nt * 8 + tc;
                    float b0 = bias[col], b1 = bias[col + 1];
                    float2 o0 = make_float2(roundtf((acc[mt][nt][0] + b0) * scale),
                                            roundtf((acc[mt][nt][1] + b1) * scale));
                    float2 o1 = make_float2(roundtf((acc[mt][nt][2] + b0) * scale),
                                            roundtf((acc[mt][nt][3] + b1) * scale));
                    *(float2*)(C + (size_t)row * QKVDIM + col)       = o0;
                    *(float2*)(C + (size_t)(row + 8) * QKVDIM + col) = o1;
#pragma unroll
                    for (int k = 0; k < 4; ++k) acc[mt][nt][k] = 0.f;
                }
            }
        }
    }
}

// ---------------------------------------------------------------------------
// Attention via TF32 mma.sync + LDSM: one block (256 thr) per bh; 2 CTAs/SM.
// SMEM (floats): Qs 128x68 @0, Ks 128x68 @8704, Vs 128x72 @17408,
//   AVG partials 256 @26624.  S (128x132) overlays Qs+Ks after QK^T.
// Inputs loaded via cp.async; V commit-group overlaps QK + softmax.
// Output staged to smem (stride 68, overlaying S) for coalesced stores.
// ---------------------------------------------------------------------------
#define AT_K_F   8704
#define AT_V_F   17408
#define AT_AVG_F 26624
#define ATTN_SMEM_BYTES ((AT_AVG_F + 256) * 4)   // 107520

__global__ void __launch_bounds__(256, 2) attn_kernel(
    const float* __restrict__ qkv, float* __restrict__ attn,
    float* __restrict__ avg_out)
{
    extern __shared__ float sm[];
    float* Vs  = sm + AT_V_F;
    float* AVG = sm + AT_AVG_F;
    float* S   = sm;                // overlays Qs+Ks after QK phase
    uint32_t sbase = smem_u32(sm);

    int bh  = blockIdx.x;
    int p   = bh >> 11;
    int rr  = bh & 2047;
    int nid = rr >> 4;
    int h   = rr & 15;
    int t   = threadIdx.x;
    int lane = t & 31;
    int wid  = t >> 5;            // 0..7
    int wm   = wid >> 2;          // 0..1
    int wn   = wid & 3;           // 0..3
    int col = h * HDIM;

    // ---- async gather of Q,K (group 1) and V (group 0, overlapped) ----
#pragma unroll
    for (int it = 0; it < 8; ++it) {
        int f  = t + it * 256;          // 0..2047
        int i  = f >> 4;                // row 0..127
        int d0 = (f & 15) << 2;         // 0..60
        int rowoff = ((2 * i + p) * 128 + nid) * QKVDIM;
        cp_async16(sbase + (i * 68 + d0) * 4,
                   qkv + rowoff + col + d0);
        cp_async16(sbase + (AT_K_F + i * 68 + d0) * 4,
                   qkv + rowoff + 1024 + col + d0);
    }
    CP_COMMIT();
#pragma unroll
    for (int it = 0; it < 8; ++it) {
        int f  = t + it * 256;
        int i  = f >> 4;
        int d0 = (f & 15) << 2;
        int rowoff = ((2 * i + p) * 128 + nid) * QKVDIM;
        cp_async16(sbase + (AT_V_F + i * 72 + d0) * 4,
                   qkv + rowoff + 2048 + col + d0);
    }
    CP_COMMIT();
    asm volatile("cp.async.wait_group 1;" ::: "memory");  // Q,K ready
    __syncthreads();

    // LDSM per-lane offsets (bytes)
    uint32_t aq_off = (uint32_t)((wm * 64 + (lane & 15)) * 272 + (lane >> 4) * 16);
    uint32_t bk_row = (uint32_t)(wn * 32 + (lane & 7) + ((lane & 16) >> 1));
    uint32_t bk_off = AT_K_F * 4 + bk_row * 272 + (((lane >> 3) & 1) * 16);

    // ---- scores = Q K^T (TF32), warp tile 64x32, K=64; kept in registers ----
    float acc[4][4][4];
#pragma unroll
    for (int i = 0; i < 4; ++i)
#pragma unroll
        for (int j = 0; j < 4; ++j)
#pragma unroll
            for (int k = 0; k < 4; ++k) acc[i][j][k] = 0.f;

#pragma unroll
    for (int ks = 0; ks < 64; ks += 8) {
        uint32_t fa[4][4], fbp[2][4];
#pragma unroll
        for (int mt = 0; mt < 4; ++mt)
            ldsm4(fa[mt], sbase + aq_off + mt * (16 * 272) + ks * 4);
#pragma unroll
        for (int ntp = 0; ntp < 2; ++ntp)
            ldsm4(fbp[ntp], sbase + bk_off + ntp * (16 * 272) + ks * 4);
#pragma unroll
        for (int mt = 0; mt < 4; ++mt) {
#pragma unroll
            for (int nt = 0; nt < 4; ++nt) {
                int np = nt >> 1, hh = (nt & 1) * 2;
                mma_tf32(acc[mt][nt], fa[mt], fbp[np][hh], fbp[np][hh + 1]);
            }
        }
    }
    __syncthreads();   // all warps done reading Qs/Ks before S overlays them

    {
        int qr = lane >> 2, tc = (lane & 3) * 2;
#pragma unroll
        for (int mt = 0; mt < 4; ++mt) {
#pragma unroll
            for (int nt = 0; nt < 4; ++nt) {
                int row = wm * 64 + mt * 16 + qr;
                int cc  = wn * 32 + nt * 8 + tc;
                S[row * 132 + cc]           = acc[mt][nt][0];
                S[row * 132 + cc + 1]       = acc[mt][nt][1];
                S[(row + 8) * 132 + cc]     = acc[mt][nt][2];
                S[(row + 8) * 132 + cc + 1] = acc[mt][nt][3];
            }
        }
    }
    __syncthreads();

    // ---- softmax: 16 rows per warp, lane-parallel; store tf32-rounded P ----
#pragma unroll
    for (int r8 = 0; r8 < 16; ++r8) {
        int row = wid * 16 + r8;
        float4 v = *(float4*)&S[row * 132 + lane * 4];
        float mx = fmaxf(fmaxf(v.x, v.y), fmaxf(v.z, v.w));
#pragma unroll
        for (int o = 16; o > 0; o >>= 1)
            mx = fmaxf(mx, __shfl_xor_sync(0xffffffffu, mx, o));
        v.x = __expf(v.x - mx); v.y = __expf(v.y - mx);
        v.z = __expf(v.z - mx); v.w = __expf(v.w - mx);
        float sum = v.x + v.y + v.z + v.w;
#pragma unroll
        for (int o = 16; o > 0; o >>= 1)
            sum += __shfl_xor_sync(0xffffffffu, sum, o);
        float inv = 1.0f / sum;
        v.x = roundtf(v.x * inv); v.y = roundtf(v.y * inv);
        v.z = roundtf(v.z * inv); v.w = roundtf(v.w * inv);
        *(float4*)&S[row * 132 + lane * 4] = v;
    }
    __syncthreads();

    // ---- avg_w partials; V must be resident before AV ----
    {
        int colx = t & 127;
        int half = t >> 7;          // 0 or 1
        int i0 = half * 64;
        float s0 = 0.f, s1 = 0.f;
#pragma unroll 8
        for (int i = 0; i < 64; i += 2) {
            s0 += S[(i0 + i) * 132 + colx];
            s1 += S[(i0 + i + 1) * 132 + colx];
        }
        AVG[t] = s0 + s1;
    }
    asm volatile("cp.async.wait_group 0;" ::: "memory");  // V ready
    __syncthreads();
    if (t < 128)
        avg_out[bh * 128 + t] = (AVG[t] + AVG[t + 128]) * 0.0625f;

    // ---- A·V (TF32): A = S via LDSM, warp tile 64x16, K=128 ----
    float av[4][2][4];
    {
        int fr = lane >> 2;
        int fc = lane & 3;
        uint32_t as_off = (uint32_t)((wm * 64 + (lane & 15)) * 528 + (lane >> 4) * 16);
#pragma unroll
        for (int i = 0; i < 4; ++i)
#pragma unroll
            for (int j = 0; j < 2; ++j)
#pragma unroll
                for (int k = 0; k < 4; ++k) av[i][j][k] = 0.f;

#pragma unroll
        for (int ks = 0; ks < 128; ks += 8) {
            uint32_t fa[4][4], fb[2][2];
#pragma unroll
            for (int mt = 0; mt < 4; ++mt)
                ldsm4(fa[mt], sbase + as_off + mt * (16 * 528) + ks * 4);
#pragma unroll
            for (int nt = 0; nt < 2; ++nt) {
                int nb = wn * 16 + nt * 8 + fr;
                fb[nt][0] = __float_as_uint(Vs[(ks + fc) * 72 + nb]);
                fb[nt][1] = __float_as_uint(Vs[(ks + fc + 4) * 72 + nb]);
            }
#pragma unroll
            for (int mt = 0; mt < 4; ++mt)
#pragma unroll
                for (int nt = 0; nt < 2; ++nt)
                    mma_tf32(av[mt][nt], fa[mt], fb[nt][0], fb[nt][1]);
        }
    }
    __syncthreads();   // everyone done reading S before OUT overlays it

    // ---- stage output in smem (stride 68), then coalesced global stores ----
    {
        int qr = lane >> 2, tc = (lane & 3) * 2;
#pragma unroll
        for (int mt = 0; mt < 4; ++mt) {
#pragma unroll
            for (int nt = 0; nt < 2; ++nt) {
                int row = wm * 64 + mt * 16 + qr;
                int cc  = wn * 16 + nt * 8 + tc;
                *(float2*)&S[row * 68 + cc] =
                    make_float2(av[mt][nt][0], av[mt][nt][1]);
                *(float2*)&S[(row + 8) * 68 + cc] =
                    make_float2(av[mt][nt][2], av[mt][nt][3]);
            }
        }
    }
    __syncthreads();
#pragma unroll
    for (int it = 0; it < 8; ++it) {
        int f  = t + it * 256;
        int row = f >> 4;
        int c4  = (f & 15) << 2;
        float4 v = *(float4*)&S[row * 68 + c4];
        int orow = (2 * row + p) * 128 + nid;
        *(float4*)&attn[(size_t)orow * EDIM + col + c4] = v;
    }
}

// ---------------------------------------------------------------------------
// Launch
// ---------------------------------------------------------------------------
extern "C" void kernel_launch(void* const* d_in, const int* in_sizes, int n_in,
                              void* d_out, int out_size)
{
    const float* x    = (const float*)d_in[0];
    const float* ln1w = (const float*)d_in[1];
    const float* ln1b = (const float*)d_in[2];
    const float* inw  = (const float*)d_in[3];
    const float* inb  = (const float*)d_in[4];
    const float* ln2w = (const float*)d_in[5];
    const float* ln2b = (const float*)d_in[6];
    float* out = (float*)d_out;

    float *xn, *qkv, *attn, *wtf;
    cudaGetSymbolAddress((void**)&xn,   g_xn);
    cudaGetSymbolAddress((void**)&qkv,  g_qkv);
    cudaGetSymbolAddress((void**)&attn, g_attn);
    cudaGetSymbolAddress((void**)&wtf,  g_wtf);

    cudaFuncSetAttribute(attn_kernel,
                         cudaFuncAttributeMaxDynamicSharedMemorySize,
                         ATTN_SMEM_BYTES);
    cudaFuncSetAttribute(qkv_gemm_tf32_kernel,
                         cudaFuncAttributeMaxDynamicSharedMemorySize,
                         GS_SMEM);
    cudaFuncSetAttribute(permute_w_kernel,
                         cudaFuncAttributeMaxDynamicSharedMemorySize,
                         PW_SMEM);

    // 1) xn = LN1(x), tf32-rounded (also the residual for LN2)
    ln_kernel<<<NROWS, 256>>>(x, nullptr, ln1w, ln1b, xn, 1);
    // 2) permute + round weights into B-fragment layout
    permute_w_kernel<<<192, 256, PW_SMEM>>>(inw, wtf);
    // 3) persistent TF32 QKV GEMM (pipeline runs across tiles)
    qkv_gemm_tf32_kernel<<<NSM, 256, GS_SMEM>>>(xn, wtf, inb, qkv);
    // 4) TF32 attention + avg_w (2 CTAs/SM, async loads, coalesced epilogue)
    attn_kernel<<<NBH, 256, ATTN_SMEM_BYTES>>>(qkv, attn, out + OUT_ELEMS);
    // 5) out = LN2(xn + attn)
    ln_kernel<<<NROWS, 256>>>(xn, attn, ln2w, ln2b, out, 0);
}